// round 10
// baseline (speedup 1.0000x reference)
#include <cuda_runtime.h>
#include <math.h>

#define NC 80
#define CLS_C 720
#define REG_C 36
#define DPI 100
#define BATCH 4
#define CAPB 131072

// -------- level tables --------
__constant__ int cb_W[4]   = {64,32,16,8};
__constant__ int cb_HW[4]  = {4096,1024,256,64};
__constant__ int cb_LW[4]  = {6,5,4,3};
__constant__ int cb_CUM[4] = {0,4096,5120,5376};
__constant__ int cb_lvl[43] = {0,0,0,0,0,0,0,0,0,0,0,0,0,0,0,0,
                               0,0,0,0,0,0,0,0,0,0,0,0,0,0,0,0,
                               1,1,1,1,1,1,1,1, 2,2, 3};
__constant__ int cb_pix[43] = {0,128,256,384,512,640,768,896,1024,1152,1280,1408,
                               1536,1664,1792,1920,2048,2176,2304,2432,2560,2688,
                               2816,2944,3072,3200,3328,3456,3584,3712,3840,3968,
                               0,128,256,384,512,640,768,896, 0,128, 0};

__device__ __constant__ float c_sizes[4][3] = {
    {32.f,40.f,50.f},{64.f,80.f,101.f},{128.f,161.f,203.f},{256.f,322.f,406.f}};
__device__ __constant__ float c_ratios[3] = {0.5f,1.0f,2.0f};
__device__ __constant__ int   c_str[4] = {8,16,32,64};

#define OFF_CLS_TW 0
#define OFF_REG_TW 2359296
#define OFF_CLS_OW 4718592
#define OFF_REG_OW 6488064
#define WT_TOTAL   6782976

// -------- scratch --------
__device__ __align__(16) float g_xh0[(size_t)8*5440*256];
__device__ __align__(16) float g_xl0[(size_t)8*5440*256];
__device__ __align__(16) float g_xh1[(size_t)8*5440*256];
__device__ __align__(16) float g_xl1[(size_t)8*5440*256];
__device__ __align__(16) float g_wth[WT_TOTAL];
__device__ __align__(16) float g_wtl[WT_TOTAL];
__device__ __align__(16) float g_cls[BATCH*CLS_C*5440];
__device__ __align__(16) float g_reg[BATCH*REG_C*5440];
__device__ unsigned g_hist[16*65536];
__device__ unsigned g_thr[16];
__device__ int      g_cnt[16];
__device__ unsigned long long g_cand[(size_t)16*CAPB];
__device__ unsigned long long g_sel[16*DPI];
__device__ float g_cbox[BATCH*400*4];
__device__ float g_cscore[BATCH*400];
__device__ int   g_clab[BATCH*400];

__device__ __forceinline__ unsigned fkey(float f){
    unsigned b=__float_as_uint(f);
    return b ^ ((b>>31) ? 0xFFFFFFFFu : 0x80000000u);
}
__device__ __forceinline__ float unfkey(unsigned u){
    unsigned b=u ^ ((u>>31) ? 0x80000000u : 0xFFFFFFFFu);
    return __uint_as_float(b);
}
__device__ __forceinline__ float tf32_hi(float x){
    unsigned r;
    asm("cvt.rna.tf32.f32 %0, %1;" : "=r"(r) : "f"(x));
    return __uint_as_float(r);
}
__device__ __forceinline__ void mma_tf32(float* c, const unsigned* a,
                                         unsigned b0, unsigned b1){
    asm("mma.sync.aligned.m16n8k8.row.col.f32.tf32.tf32.f32 "
        "{%0,%1,%2,%3},{%4,%5,%6,%7},{%8,%9},{%0,%1,%2,%3};"
        : "+f"(c[0]),"+f"(c[1]),"+f"(c[2]),"+f"(c[3])
        : "r"(a[0]),"r"(a[1]),"r"(a[2]),"r"(a[3]),"r"(b0),"r"(b1));
}

// -------- prep: transpose + split fp32 [b][ci][pix] -> [b][pixG][ci] tf32 hi/lo
__global__ void prep_k(const float* __restrict__ f0,const float* __restrict__ f1,
                       const float* __restrict__ f2,const float* __restrict__ f3,
                       float* __restrict__ oh,float* __restrict__ ol){
    size_t total=(size_t)4*5440*256;
    for(size_t e=(size_t)blockIdx.x*blockDim.x+threadIdx.x;e<total;
        e+=(size_t)gridDim.x*blockDim.x){
        int ci=(int)(e&255);
        int pixG=(int)((e>>8)%5440);
        int b=(int)(e/(5440*256));
        int lvl = pixG<4096?0 : pixG<5120?1 : pixG<5376?2 : 3;
        int cum = lvl==0?0 : lvl==1?4096 : lvl==2?5120 : 5376;
        int HW  = lvl==0?4096 : lvl==1?1024 : lvl==2?256 : 64;
        const float* f = lvl==0?f0 : lvl==1?f1 : lvl==2?f2 : f3;
        float v = f[((size_t)b*256+ci)*HW + (pixG-cum)];
        float h = tf32_hi(v);
        oh[e]=h; ol[e]=tf32_hi(v-h);
    }
}

// -------- weight transform+split: (L,Cout,256,3,3) -> [L][kpos][CoPad][ci] tf32 hi/lo
__global__ void wtrans_k(const float* __restrict__ src,
                         float* __restrict__ dh, float* __restrict__ dl,
                         int Cout,int CoPad,int nL){
    size_t total=(size_t)nL*9*CoPad*256;
    for(size_t e=(size_t)blockIdx.x*blockDim.x+threadIdx.x;e<total;
        e+=(size_t)gridDim.x*blockDim.x){
        int ci=(int)(e&255); size_t t=e>>8;
        int co=(int)(t%CoPad); t/=CoPad;
        int kpos=(int)(t%9); int layer=(int)(t/9);
        float v=0.f;
        if(co<Cout) v=src[(((size_t)layer*Cout+co)*256+ci)*9+kpos];
        float h=tf32_hi(v);
        dh[e]=h; dl[e]=tf32_hi(v-h);
    }
}

// ===================== 3xTF32 mma conv core =====================
// A=W[128co][k], B=X[128px][k] (both k-contig), D[co][px] fp32 in regs.
#define SMEMBYTES 73728   // 4 tiles of 128*36 floats = 18432 floats = 73728 bytes

__device__ void conv_mma(
    const float* __restrict__ Xh, const float* __restrict__ Xl,
    const float* __restrict__ Wh, const float* __restrict__ Wl,
    int CoPad, int coBase, const float* __restrict__ bias,
    int W, int HW, int lw, int pixBase,
    int mode, int Cout, int relu,
    float* __restrict__ outA, float* __restrict__ outB,
    int cum, float* smem)
{
    float* Wh_s = smem;
    float* Wl_s = smem + 4608;
    float* Xh_s = smem + 9216;
    float* Xl_s = smem + 13824;

    const int tid=threadIdx.x;
    const int lane=tid&31, wid=tid>>5;
    const int wm=wid&1, wn=wid>>1;
    const int lr=lane>>2, lc=lane&3;

    int validPx = HW - pixBase; if(validPx>128) validPx=128;

    const int srow = tid>>1;
    const int khalf = (tid&1)<<4;
    const int q = pixBase + srow;
    const bool rowv = srow < validPx;
    const int hh = q>>lw, ww = q&(W-1);

    float acc[4][4][4];
#pragma unroll
    for(int i=0;i<4;i++)
#pragma unroll
        for(int j=0;j<4;j++)
#pragma unroll
            for(int r=0;r<4;r++) acc[i][j][r]=0.f;

    const float4 z4 = make_float4(0.f,0.f,0.f,0.f);

    for(int kpos=0;kpos<9;kpos++){
        const int dh=kpos/3-1, dw=kpos-(kpos/3)*3-1;
        const int hs=hh+dh, ws=ww+dw;
        const bool ok = rowv && (unsigned)hs<(unsigned)W && (unsigned)ws<(unsigned)W;
        const size_t xoff = ok ? ((size_t)(hs*W+ws)*256) : 0;
        const size_t woff = ((size_t)kpos*CoPad + coBase + srow)*256;
        for(int c0=0;c0<256;c0+=32){
#pragma unroll
            for(int i=0;i<4;i++){
                *(float4*)&Wh_s[srow*36+khalf+i*4] =
                    *(const float4*)(Wh + woff + c0 + khalf + i*4);
                *(float4*)&Wl_s[srow*36+khalf+i*4] =
                    *(const float4*)(Wl + woff + c0 + khalf + i*4);
            }
#pragma unroll
            for(int i=0;i<4;i++){
                float4 vh = ok ? *(const float4*)(Xh + xoff + c0 + khalf + i*4) : z4;
                float4 vl = ok ? *(const float4*)(Xl + xoff + c0 + khalf + i*4) : z4;
                *(float4*)&Xh_s[srow*36+khalf+i*4] = vh;
                *(float4*)&Xl_s[srow*36+khalf+i*4] = vl;
            }
            __syncthreads();
#pragma unroll
            for(int kk=0;kk<32;kk+=8){
                unsigned ah[4][4], al[4][4];
#pragma unroll
                for(int fm=0;fm<4;fm++){
                    int mr=(wm<<6)+(fm<<4)+lr;
                    const float* ph=&Wh_s[mr*36+kk+lc];
                    ah[fm][0]=__float_as_uint(ph[0]);
                    ah[fm][1]=__float_as_uint(ph[8*36]);
                    ah[fm][2]=__float_as_uint(ph[4]);
                    ah[fm][3]=__float_as_uint(ph[8*36+4]);
                    const float* pl=&Wl_s[mr*36+kk+lc];
                    al[fm][0]=__float_as_uint(pl[0]);
                    al[fm][1]=__float_as_uint(pl[8*36]);
                    al[fm][2]=__float_as_uint(pl[4]);
                    al[fm][3]=__float_as_uint(pl[8*36+4]);
                }
#pragma unroll
                for(int fn=0;fn<4;fn++){
                    int nr=(wn<<5)+(fn<<3)+lr;
                    const float* qh=&Xh_s[nr*36+kk+lc];
                    unsigned bh0=__float_as_uint(qh[0]);
                    unsigned bh1=__float_as_uint(qh[4]);
                    const float* ql=&Xl_s[nr*36+kk+lc];
                    unsigned bl0=__float_as_uint(ql[0]);
                    unsigned bl1=__float_as_uint(ql[4]);
#pragma unroll
                    for(int fm=0;fm<4;fm++){
                        mma_tf32(acc[fm][fn], ah[fm], bh0, bh1);
                        mma_tf32(acc[fm][fn], ah[fm], bl0, bl1);
                        mma_tf32(acc[fm][fn], al[fm], bh0, bh1);
                    }
                }
            }
            __syncthreads();
        }
    }
#pragma unroll
    for(int fm=0;fm<4;fm++){
#pragma unroll
        for(int fn=0;fn<4;fn++){
            int m0=(wm<<6)+(fm<<4)+lr;
            int n0=(wn<<5)+(fn<<3)+(lc<<1);
            const float* a=acc[fm][fn];
#pragma unroll
            for(int r=0;r<4;r++){
                int m=m0+((r>>1)<<3);
                int n=n0+(r&1);
                if(n>=validPx) continue;
                int co=coBase+m;
                if(mode==0){
                    float v=a[r]+bias[co];
                    if(relu) v=fmaxf(v,0.f);
                    float h=tf32_hi(v);
                    size_t ad=((size_t)(cum+pixBase+n))*256+co;
                    outA[ad]=h; outB[ad]=tf32_hi(v-h);
                }else{
                    if(co<Cout)
                        outA[(size_t)co*HW + pixBase + n]=a[r]+bias[co];
                }
            }
        }
    }
}

// -------- tower layer kernel
__global__ __launch_bounds__(256,2)
void conv_tower_k(const float* __restrict__ Xh,const float* __restrict__ Xl,
                  const float* __restrict__ wCh,const float* __restrict__ wCl,
                  const float* __restrict__ wRh,const float* __restrict__ wRl,
                  const float* __restrict__ bC,const float* __restrict__ bR,
                  float* __restrict__ XhO,float* __restrict__ XlO,int first){
    extern __shared__ float smem[];
    const int bx=blockIdx.x;
    const int lvl=cb_lvl[bx], pixBase=cb_pix[bx];
    const int tower=blockIdx.y>>1, coBase=(blockIdx.y&1)<<7;
    const int b=blockIdx.z;
    const int W=cb_W[lvl],HW=cb_HW[lvl],lw=cb_LW[lvl],cum=cb_CUM[lvl];
    int inSlot = first ? b : (tower*4+b);
    int outSlot = tower*4+b;
    conv_mma(Xh+(size_t)inSlot*5440*256+(size_t)cum*256,
             Xl+(size_t)inSlot*5440*256+(size_t)cum*256,
             tower?wRh:wCh, tower?wRl:wCl, 256, coBase, tower?bR:bC,
             W,HW,lw,pixBase, 0,256,1,
             XhO+(size_t)outSlot*5440*256, XlO+(size_t)outSlot*5440*256,
             cum, smem);
}

// -------- heads: y<6 cls (720ch), y==6 reg (36ch)
__global__ __launch_bounds__(256,2)
void conv_head_k(const float* __restrict__ Xh,const float* __restrict__ Xl,
                 const float* __restrict__ wCh,const float* __restrict__ wCl,
                 const float* __restrict__ wRh,const float* __restrict__ wRl,
                 const float* __restrict__ cob,const float* __restrict__ rob,
                 float* __restrict__ cls,float* __restrict__ reg){
    extern __shared__ float smem[];
    const int bx=blockIdx.x;
    const int lvl=cb_lvl[bx], pixBase=cb_pix[bx];
    const int y=blockIdx.y, b=blockIdx.z;
    const int W=cb_W[lvl],HW=cb_HW[lvl],lw=cb_LW[lvl],cum=cb_CUM[lvl];
    if(y<6){
        conv_mma(Xh+(size_t)b*5440*256+(size_t)cum*256,
                 Xl+(size_t)b*5440*256+(size_t)cum*256,
                 wCh, wCl, 768, y*128, cob,
                 W,HW,lw,pixBase, 1,720,0,
                 cls + (size_t)CLS_C*4*cum + (size_t)b*CLS_C*HW, 0, cum, smem);
    }else{
        conv_mma(Xh+(size_t)(4+b)*5440*256+(size_t)cum*256,
                 Xl+(size_t)(4+b)*5440*256+(size_t)cum*256,
                 wRh, wRl, 128, 0, rob,
                 W,HW,lw,pixBase, 1,36,0,
                 reg + (size_t)REG_C*4*cum + (size_t)b*REG_C*HW, 0, cum, smem);
    }
}

// ===================== selection (unchanged, validated) =====================
__device__ __forceinline__ float sigm(float v){ return 1.0f/(1.0f+expf(-v)); }
__device__ __forceinline__ bool is_cand(float v){
    if(v>-2.93f) return true;
    if(v<=-2.96f) return false;
    return sigm(v)>0.05f;
}

__global__ void zero_k(){
    int i=blockIdx.x*blockDim.x+threadIdx.x;
    if(i<16*65536) g_hist[i]=0;
    if(i<16) g_cnt[i]=0;
}

__global__ void hist_k(const float* __restrict__ cls){
    const int g=blockIdx.y, b=g>>2, lvl=g&3;
    const int HW=cb_HW[lvl], n=CLS_C*HW;
    const float* p=cls + (size_t)CLS_C*4*cb_CUM[lvl] + (size_t)b*n;
    for(int m=blockIdx.x*blockDim.x+threadIdx.x;m<n;m+=gridDim.x*blockDim.x){
        float v=p[m];
        if(is_cand(v)) atomicAdd(&g_hist[g*65536+(fkey(sigm(v))>>16)],1u);
    }
}

__global__ void scan_k(){
    const int g=blockIdx.x;
    __shared__ unsigned seg[256];
    const unsigned* h=&g_hist[g*65536];
    unsigned s=0; int base=threadIdx.x*256;
    for(int k=0;k<256;k++) s+=h[65535-(base+k)];
    seg[threadIdx.x]=s;
    __syncthreads();
    if(threadIdx.x==0){
        unsigned cum=0,thr=0;
        for(int sg=0;sg<256;sg++){
            if(cum+seg[sg]>=DPI){
                for(int k=0;k<256;k++){
                    cum+=h[65535-(sg*256+k)];
                    if(cum>=DPI){thr=65535-(sg*256+k);break;}
                }
                break;
            }
            cum+=seg[sg];
        }
        g_thr[g]=thr;
    }
}

__global__ void collect_k(const float* __restrict__ cls){
    const int g=blockIdx.y, b=g>>2, lvl=g&3;
    const int HW=cb_HW[lvl], n=CLS_C*HW;
    const unsigned thr=g_thr[g];
    const float* p=cls + (size_t)CLS_C*4*cb_CUM[lvl] + (size_t)b*n;
    for(int m=blockIdx.x*blockDim.x+threadIdx.x;m<n;m+=gridDim.x*blockDim.x){
        float v=p[m];
        if(!is_cand(v)) continue;
        unsigned u=fkey(sigm(v));
        if((u>>16)>=thr){
            int pos=atomicAdd(&g_cnt[g],1);
            if(pos<CAPB){
                int co=m/HW, pix=m-co*HW;
                unsigned nn=(unsigned)(pix*CLS_C+co);
                g_cand[(size_t)g*CAPB+pos]=((unsigned long long)u<<32)|(0xFFFFFFFFu-nn);
            }
        }
    }
}

__global__ __launch_bounds__(256)
void select_k(){
    const int g=blockIdx.x;
    int cnt=g_cnt[g]; if(cnt>CAPB) cnt=CAPB;
    unsigned long long* cand=&g_cand[(size_t)g*CAPB];
    __shared__ unsigned long long sc[4096];
    __shared__ unsigned long long wmax[8];
    __shared__ int wpos[8];
    const int tid=threadIdx.x, lane=tid&31, wid=tid>>5;
    const bool cached = cnt<=4096;
    if(cached) for(int i=tid;i<cnt;i+=256) sc[i]=cand[i];
    __syncthreads();
    unsigned long long* src = cached? sc : cand;
    for(int r=0;r<DPI;r++){
        unsigned long long mk=0ULL; int mp=-1;
        for(int i=tid;i<cnt;i+=256){
            unsigned long long k=src[i];
            if(k>mk){mk=k;mp=i;}
        }
#pragma unroll
        for(int off=16;off>0;off>>=1){
            unsigned long long ok=__shfl_down_sync(0xFFFFFFFFu,mk,off);
            int op=__shfl_down_sync(0xFFFFFFFFu,mp,off);
            if(ok>mk){mk=ok;mp=op;}
        }
        if(lane==0){wmax[wid]=mk;wpos[wid]=mp;}
        __syncthreads();
        if(tid==0){
            unsigned long long bk=wmax[0]; int bp=wpos[0];
#pragma unroll
            for(int w=1;w<8;w++) if(wmax[w]>bk){bk=wmax[w];bp=wpos[w];}
            g_sel[g*DPI+r]=bk;
            if(bp>=0) src[bp]=0ULL;
        }
        __syncthreads();
    }
}

__global__ void decode_k(const float* __restrict__ reg,
                         const int* __restrict__ ph,const int* __restrict__ pw){
    const int g=blockIdx.x, b=g>>2, lvl=g&3;
    const int r=threadIdx.x;
    if(r>=DPI) return;
    const int W=cb_W[lvl], HW=cb_HW[lvl];
    const float ih=(float)(*ph), iw=(float)(*pw);
    const int slot=b*400+lvl*DPI+r;
    unsigned long long k=g_sel[g*DPI+r];
    float* bx=&g_cbox[(size_t)slot*4];
    if(!k){ g_cscore[slot]=-1.f; g_clab[slot]=-1; bx[0]=bx[1]=bx[2]=bx[3]=0.f; return; }
    float sc=unfkey((unsigned)(k>>32));
    unsigned n=0xFFFFFFFFu-(unsigned)(k&0xFFFFFFFFu);
    int pix=(int)(n/CLS_C); int co=(int)(n-(unsigned)pix*CLS_C);
    int a=co/NC, c=co-a*NC;
    int hh=pix/W, ww=pix-hh*W;
    float size=c_sizes[lvl][a%3];
    float hr=sqrtf(c_ratios[a/3]);
    float wr=1.f/hr;
    float ws=wr*size, hs=hr*size;
    float st=(float)c_str[lvl];
    float sx=(float)ww*st, sy=(float)hh*st;
    float ax1=fminf(fmaxf(sx+rintf(-ws*0.5f),0.f),iw);
    float ay1=fminf(fmaxf(sy+rintf(-hs*0.5f),0.f),ih);
    float ax2=fminf(fmaxf(sx+rintf( ws*0.5f),0.f),iw);
    float ay2=fminf(fmaxf(sy+rintf( hs*0.5f),0.f),ih);
    float aw=ax2-ax1, ah=ay2-ay1;
    float cx=ax1+0.5f*aw, cy=ay1+0.5f*ah;
    const float* R=reg + (size_t)REG_C*4*cb_CUM[lvl] + (size_t)b*REG_C*HW;
    float dx=R[(a*4+0)*HW+pix];
    float dy=R[(a*4+1)*HW+pix];
    const float CLIPV=(float)4.135166556742356;
    float dw=fminf(R[(a*4+2)*HW+pix],CLIPV);
    float dh=fminf(R[(a*4+3)*HW+pix],CLIPV);
    float pcx=dx*aw+cx, pcy=dy*ah+cy;
    float pw_=expf(dw)*aw, ph_=expf(dh)*ah;
    bx[0]=fminf(fmaxf(pcx-0.5f*pw_,0.f),iw);
    bx[1]=fminf(fmaxf(pcy-0.5f*ph_,0.f),ih);
    bx[2]=fminf(fmaxf(pcx+0.5f*pw_,0.f),iw);
    bx[3]=fminf(fmaxf(pcy+0.5f*ph_,0.f),ih);
    g_cscore[slot]=sc;
    g_clab[slot]=c;
}

__global__ __launch_bounds__(512)
void final_k(float* __restrict__ out,const int* __restrict__ ph,const int* __restrict__ pw){
    int b=blockIdx.x, tid=threadIdx.x;
    __shared__ unsigned long long key[512];
    __shared__ float X1[512],Y1[512],X2[512],Y2[512],AR[512],SC[512];
    __shared__ float BX1[512],BY1[512],BX2[512],BY2[512];
    __shared__ int LB[512];
    __shared__ unsigned char KP[512];
    float ih=(float)(*ph), iw=(float)(*pw);
    float ob=fmaxf(ih,iw)+1.f;
    if(tid<400)
        key[tid]=((unsigned long long)fkey(g_cscore[b*400+tid])<<32)|(0xFFFFFFFFu-(unsigned)tid);
    else key[tid]=0ULL;
    __syncthreads();
    for(int k=2;k<=512;k<<=1)
        for(int j=k>>1;j>0;j>>=1){
            int ix=tid^j;
            if(ix>tid){
                unsigned long long a=key[tid],c=key[ix];
                if((a>c)==((tid&k)==0)){key[tid]=c;key[ix]=a;}
            }
            __syncthreads();
        }
    {
        unsigned long long k=key[511-tid];
        float sc=-1.f; int lb=-1; float b0=0,b1=0,b2=0,b3=0;
        if(k){
            unsigned i=0xFFFFFFFFu-(unsigned)(k&0xFFFFFFFFu);
            sc=unfkey((unsigned)(k>>32));
            lb=g_clab[b*400+i];
            const float* bp=&g_cbox[((size_t)b*400+i)*4];
            b0=bp[0];b1=bp[1];b2=bp[2];b3=bp[3];
        }
        float o=(float)lb*ob;
        BX1[tid]=b0;BY1[tid]=b1;BX2[tid]=b2;BY2[tid]=b3;
        X1[tid]=b0+o;Y1[tid]=b1+o;X2[tid]=b2+o;Y2[tid]=b3+o;
        SC[tid]=sc;LB[tid]=lb;
        AR[tid]=(X2[tid]-X1[tid])*(Y2[tid]-Y1[tid]);
        KP[tid]=(sc>0.05f)?1:0;
    }
    __syncthreads();
    for(int i=0;i<400;i++){
        if(KP[i]&&tid>i&&tid<400&&KP[tid]){
            float w=fmaxf(fminf(X2[i],X2[tid])-fmaxf(X1[i],X1[tid]),0.f);
            float h=fmaxf(fminf(Y2[i],Y2[tid])-fmaxf(Y1[i],Y1[tid]),0.f);
            float it=w*h;
            float iou=it/(AR[i]+AR[tid]-it+1e-9f);
            if(iou>0.5f) KP[tid]=0;
        }
        __syncthreads();
    }
    if(tid==0){
        int o=0;
        for(int r=0;r<400&&o<DPI;r++) if(KP[r]){
            out[(b*DPI+o)*4+0]=BX1[r]; out[(b*DPI+o)*4+1]=BY1[r];
            out[(b*DPI+o)*4+2]=BX2[r]; out[(b*DPI+o)*4+3]=BY2[r];
            out[1600+b*DPI+o]=SC[r];   out[2000+b*DPI+o]=(float)LB[r];
            o++;
        }
        for(;o<DPI;o++){
            out[(b*DPI+o)*4+0]=0.f; out[(b*DPI+o)*4+1]=0.f;
            out[(b*DPI+o)*4+2]=0.f; out[(b*DPI+o)*4+3]=0.f;
            out[1600+b*DPI+o]=0.f;  out[2000+b*DPI+o]=-1.f;
        }
    }
}

extern "C" void kernel_launch(void* const* d_in, const int* in_sizes, int n_in,
                              void* d_out, int out_size){
    const float* f0=(const float*)d_in[0];
    const float* f1=(const float*)d_in[1];
    const float* f2=(const float*)d_in[2];
    const float* f3=(const float*)d_in[3];
    const float* ctw=(const float*)d_in[4];
    const float* ctb=(const float*)d_in[5];
    const float* cow=(const float*)d_in[6];
    const float* cob=(const float*)d_in[7];
    const float* rtw=(const float*)d_in[8];
    const float* rtb=(const float*)d_in[9];
    const float* row_=(const float*)d_in[10];
    const float* rob=(const float*)d_in[11];
    const int* ph=(const int*)d_in[12];
    const int* pw=(const int*)d_in[13];

    float *xh0,*xl0,*xh1,*xl1,*cls,*reg,*wh,*wl;
    cudaGetSymbolAddress((void**)&xh0,g_xh0);
    cudaGetSymbolAddress((void**)&xl0,g_xl0);
    cudaGetSymbolAddress((void**)&xh1,g_xh1);
    cudaGetSymbolAddress((void**)&xl1,g_xl1);
    cudaGetSymbolAddress((void**)&cls,g_cls);
    cudaGetSymbolAddress((void**)&reg,g_reg);
    cudaGetSymbolAddress((void**)&wh,g_wth);
    cudaGetSymbolAddress((void**)&wl,g_wtl);

    cudaFuncSetAttribute(conv_tower_k, cudaFuncAttributeMaxDynamicSharedMemorySize, SMEMBYTES);
    cudaFuncSetAttribute(conv_head_k,  cudaFuncAttributeMaxDynamicSharedMemorySize, SMEMBYTES);

    prep_k<<<2048,256>>>(f0,f1,f2,f3,xh0,xl0);
    wtrans_k<<<2048,256>>>(ctw, wh+OFF_CLS_TW, wl+OFF_CLS_TW, 256,256,4);
    wtrans_k<<<2048,256>>>(rtw, wh+OFF_REG_TW, wl+OFF_REG_TW, 256,256,4);
    wtrans_k<<<2048,256>>>(cow, wh+OFF_CLS_OW, wl+OFF_CLS_OW, 720,768,1);
    wtrans_k<<<1024,256>>>(row_, wh+OFF_REG_OW, wl+OFF_REG_OW, 36,128,1);

    const size_t LSZ = 589824;
    conv_tower_k<<<dim3(43,4,BATCH),256,SMEMBYTES>>>(xh0,xl0,
        wh+OFF_CLS_TW+0*LSZ, wl+OFF_CLS_TW+0*LSZ,
        wh+OFF_REG_TW+0*LSZ, wl+OFF_REG_TW+0*LSZ, ctb+0,  rtb+0,  xh1,xl1, 1);
    conv_tower_k<<<dim3(43,4,BATCH),256,SMEMBYTES>>>(xh1,xl1,
        wh+OFF_CLS_TW+1*LSZ, wl+OFF_CLS_TW+1*LSZ,
        wh+OFF_REG_TW+1*LSZ, wl+OFF_REG_TW+1*LSZ, ctb+256,rtb+256,xh0,xl0, 0);
    conv_tower_k<<<dim3(43,4,BATCH),256,SMEMBYTES>>>(xh0,xl0,
        wh+OFF_CLS_TW+2*LSZ, wl+OFF_CLS_TW+2*LSZ,
        wh+OFF_REG_TW+2*LSZ, wl+OFF_REG_TW+2*LSZ, ctb+512,rtb+512,xh1,xl1, 0);
    conv_tower_k<<<dim3(43,4,BATCH),256,SMEMBYTES>>>(xh1,xl1,
        wh+OFF_CLS_TW+3*LSZ, wl+OFF_CLS_TW+3*LSZ,
        wh+OFF_REG_TW+3*LSZ, wl+OFF_REG_TW+3*LSZ, ctb+768,rtb+768,xh0,xl0, 0);
    conv_head_k<<<dim3(43,7,BATCH),256,SMEMBYTES>>>(xh0,xl0,
        wh+OFF_CLS_OW, wl+OFF_CLS_OW, wh+OFF_REG_OW, wl+OFF_REG_OW,
        cob, rob, cls, reg);

    zero_k<<<4096,256>>>();
    hist_k<<<dim3(256,16),256>>>(cls);
    scan_k<<<16,256>>>();
    collect_k<<<dim3(256,16),256>>>(cls);
    select_k<<<16,256>>>();
    decode_k<<<16,128>>>(reg,ph,pw);
    final_k<<<BATCH,512>>>((float*)d_out,ph,pw);
}

// round 11
// speedup vs baseline: 1.1589x; 1.1589x over previous
#include <cuda_runtime.h>
#include <math.h>

#define NC 80
#define CLS_C 720
#define REG_C 36
#define DPI 100
#define BATCH 4
#define CAPB 131072

// -------- level tables --------
__constant__ int cb_W[4]   = {64,32,16,8};
__constant__ int cb_HW[4]  = {4096,1024,256,64};
__constant__ int cb_LW[4]  = {6,5,4,3};
__constant__ int cb_CUM[4] = {0,4096,5120,5376};
__constant__ int cb_lvl[43] = {0,0,0,0,0,0,0,0,0,0,0,0,0,0,0,0,
                               0,0,0,0,0,0,0,0,0,0,0,0,0,0,0,0,
                               1,1,1,1,1,1,1,1, 2,2, 3};
__constant__ int cb_pix[43] = {0,128,256,384,512,640,768,896,1024,1152,1280,1408,
                               1536,1664,1792,1920,2048,2176,2304,2432,2560,2688,
                               2816,2944,3072,3200,3328,3456,3584,3712,3840,3968,
                               0,128,256,384,512,640,768,896, 0,128, 0};

__device__ __constant__ float c_sizes[4][3] = {
    {32.f,40.f,50.f},{64.f,80.f,101.f},{128.f,161.f,203.f},{256.f,322.f,406.f}};
__device__ __constant__ float c_ratios[3] = {0.5f,1.0f,2.0f};
__device__ __constant__ int   c_str[4] = {8,16,32,64};

#define OFF_CLS_TW 0
#define OFF_REG_TW 2359296
#define OFF_CLS_OW 4718592
#define OFF_REG_OW 6488064
#define WT_TOTAL   6782976

// -------- scratch --------
__device__ __align__(16) float g_xh0[(size_t)8*5440*256];
__device__ __align__(16) float g_xl0[(size_t)8*5440*256];
__device__ __align__(16) float g_xh1[(size_t)8*5440*256];
__device__ __align__(16) float g_xl1[(size_t)8*5440*256];
__device__ __align__(16) float g_wth[WT_TOTAL];
__device__ __align__(16) float g_wtl[WT_TOTAL];
__device__ __align__(16) float g_cls[BATCH*CLS_C*5440];
__device__ __align__(16) float g_reg[BATCH*REG_C*5440];
__device__ unsigned g_hist[16*65536];
__device__ unsigned g_thr[16];
__device__ int      g_cnt[16];
__device__ unsigned long long g_cand[(size_t)16*CAPB];
__device__ unsigned long long g_sel[16*DPI];
__device__ float g_cbox[BATCH*400*4];
__device__ float g_cscore[BATCH*400];
__device__ int   g_clab[BATCH*400];

__device__ __forceinline__ unsigned fkey(float f){
    unsigned b=__float_as_uint(f);
    return b ^ ((b>>31) ? 0xFFFFFFFFu : 0x80000000u);
}
__device__ __forceinline__ float unfkey(unsigned u){
    unsigned b=u ^ ((u>>31) ? 0x80000000u : 0xFFFFFFFFu);
    return __uint_as_float(b);
}
__device__ __forceinline__ float tf32_hi(float x){
    unsigned r;
    asm("cvt.rna.tf32.f32 %0, %1;" : "=r"(r) : "f"(x));
    return __uint_as_float(r);
}
__device__ __forceinline__ void mma_tf32(float* c, const float4& a,
                                         float b0, float b1){
    asm("mma.sync.aligned.m16n8k8.row.col.f32.tf32.tf32.f32 "
        "{%0,%1,%2,%3},{%4,%5,%6,%7},{%8,%9},{%0,%1,%2,%3};"
        : "+f"(c[0]),"+f"(c[1]),"+f"(c[2]),"+f"(c[3])
        : "r"(__float_as_uint(a.x)),"r"(__float_as_uint(a.y)),
          "r"(__float_as_uint(a.z)),"r"(__float_as_uint(a.w)),
          "r"(__float_as_uint(b0)),"r"(__float_as_uint(b1)));
}
__device__ __forceinline__ unsigned smem_u32(const void* p){
    unsigned a;
    asm("{ .reg .u64 t; cvta.to.shared.u64 t, %1; cvt.u32.u64 %0, t; }"
        : "=r"(a) : "l"(p));
    return a;
}
__device__ __forceinline__ void cp16(unsigned dst, const void* src, int sz){
    asm volatile("cp.async.cg.shared.global [%0], [%1], 16, %2;"
                 :: "r"(dst), "l"(src), "r"(sz));
}
#define CP_COMMIT() asm volatile("cp.async.commit_group;" ::: "memory")
#define CP_WAIT0()  asm volatile("cp.async.wait_group 0;" ::: "memory")

// -------- prep: transpose + split fp32 [b][ci][pix] -> [b][pixG][ci] tf32 hi/lo
__global__ void prep_k(const float* __restrict__ f0,const float* __restrict__ f1,
                       const float* __restrict__ f2,const float* __restrict__ f3,
                       float* __restrict__ oh,float* __restrict__ ol){
    size_t total=(size_t)4*5440*256;
    for(size_t e=(size_t)blockIdx.x*blockDim.x+threadIdx.x;e<total;
        e+=(size_t)gridDim.x*blockDim.x){
        int ci=(int)(e&255);
        int pixG=(int)((e>>8)%5440);
        int b=(int)(e/(5440*256));
        int lvl = pixG<4096?0 : pixG<5120?1 : pixG<5376?2 : 3;
        int cum = lvl==0?0 : lvl==1?4096 : lvl==2?5120 : 5376;
        int HW  = lvl==0?4096 : lvl==1?1024 : lvl==2?256 : 64;
        const float* f = lvl==0?f0 : lvl==1?f1 : lvl==2?f2 : f3;
        float v = f[((size_t)b*256+ci)*HW + (pixG-cum)];
        float h = tf32_hi(v);
        oh[e]=h; ol[e]=tf32_hi(v-h);
    }
}

// -------- weight transform+split into FRAGMENT-MAJOR layout
// per (layer,kpos,coTile128): 8 chunk-blocks of 4096 floats; within:
// off = (((kk*2+wm)*4+fm)*32 + lane)*4 + v ; thread LDS.128 yields a0..a3
__global__ void wtrans_k(const float* __restrict__ src,
                         float* __restrict__ dh, float* __restrict__ dl,
                         int Cout,int nTiles,int nL){
    size_t total=(size_t)nL*9*nTiles*32768;
    for(size_t e=(size_t)blockIdx.x*blockDim.x+threadIdx.x;e<total;
        e+=(size_t)gridDim.x*blockDim.x){
        int off=(int)(e&4095);
        int cchunk=(int)((e>>12)&7);
        size_t t=e>>15;
        int ct=(int)(t%nTiles); t/=nTiles;
        int kpos=(int)(t%9); int layer=(int)(t/9);
        int v=off&3, lane=(off>>2)&31, fm=(off>>7)&3, wm=(off>>9)&1, kk=(off>>10)&3;
        int lr=lane>>2, lc=lane&3;
        int co=ct*128 + wm*64 + fm*16 + (v&1)*8 + lr;
        int k =cchunk*32 + kk*8 + (v>>1)*4 + lc;
        float val=0.f;
        if(co<Cout) val=src[(((size_t)layer*Cout+co)*256+k)*9+kpos];
        float h=tf32_hi(val);
        dh[e]=h; dl[e]=tf32_hi(val-h);
    }
}

// ===================== 3xTF32 mma conv core (cp.async double-buffered) =====
#define STAGEF 17408                 // floats per stage: A 8192 + B 9216
#define SMEMBYTES (2*STAGEF*4)       // 139264

__device__ void conv_mma(
    const float* __restrict__ Xh, const float* __restrict__ Xl,
    const float* __restrict__ Whf, const float* __restrict__ Wlf,
    int nTiles, int ct, const float* __restrict__ bias,
    int W, int HW, int lw, int pixBase,
    int mode, int Cout, int relu,
    float* __restrict__ outA, float* __restrict__ outB,
    int cum, float* smem)
{
    const int tid=threadIdx.x;
    const int lane=tid&31, wid=tid>>5;
    const int wm=wid&1, wn=wid>>1;
    const int lr=lane>>2, lc=lane&3;
    const int coBase=ct*128;

    int validPx = HW - pixBase; if(validPx>128) validPx=128;

    const int srow=tid>>1, half=tid&1;
    const int q=pixBase+srow;
    const bool rowv = srow<validPx;
    const int hh=q>>lw, ww=q&(W-1);

    const unsigned sb = smem_u32(smem);

    float acc[4][4][4];
#pragma unroll
    for(int i=0;i<4;i++)
#pragma unroll
        for(int j=0;j<4;j++)
#pragma unroll
            for(int r=0;r<4;r++) acc[i][j][r]=0.f;

    // ---- stage one chunk (kpos, cchunk) into buffer s
    auto stage=[&](int ch,int s){
        const int kpos=ch>>3, cc=ch&7;
        const unsigned base = sb + (unsigned)(s*STAGEF*4);
        // A (fragment-major, linear copy)
        const float* ah=Whf + ((size_t)(kpos*nTiles+ct))*32768 + cc*4096 + tid*16;
        const float* al=Wlf + ((size_t)(kpos*nTiles+ct))*32768 + cc*4096 + tid*16;
#pragma unroll
        for(int i=0;i<4;i++){
            cp16(base + (tid*16+i*4)*4,        ah+i*4, 16);
            cp16(base + (4096+tid*16+i*4)*4,   al+i*4, 16);
        }
        // B: X rows with halo, zero-fill OOB
        const int dh=kpos/3-1, dw=kpos-(kpos/3)*3-1;
        const int hs=hh+dh, ws=ww+dw;
        const bool ok = rowv && (unsigned)hs<(unsigned)W && (unsigned)ws<(unsigned)W;
        const size_t xoff = ok ? ((size_t)(hs*W+ws)*256) : 0;
        const int sz = ok?16:0;
        const float* xh = Xh + xoff + cc*32 + half*16;
        const float* xl = Xl + xoff + cc*32 + half*16;
        const unsigned bh = base + (8192  + srow*36 + half*16)*4;
        const unsigned bl = base + (12800 + srow*36 + half*16)*4;
#pragma unroll
        for(int i=0;i<4;i++){
            cp16(bh + i*16, xh+i*4, sz);
            cp16(bl + i*16, xl+i*4, sz);
        }
    };

    stage(0,0); CP_COMMIT();

    for(int ch=0;ch<72;ch++){
        const int s=ch&1;
        CP_WAIT0();
        __syncthreads();
        if(ch+1<72){ stage(ch+1, s^1); CP_COMMIT(); }
        float* S = smem + s*STAGEF;
        float* AhS=S, *AlS=S+4096, *BhS=S+8192, *BlS=S+12800;
#pragma unroll
        for(int kk=0;kk<4;kk++){
            float4 AH[4], AL[4];
#pragma unroll
            for(int fm=0;fm<4;fm++){
                const int fo=((kk*2+wm)*4+fm)*128 + lane*4;
                AH[fm]=*(const float4*)&AhS[fo];
                AL[fm]=*(const float4*)&AlS[fo];
            }
#pragma unroll
            for(int fn=0;fn<4;fn++){
                const int nr=(wn<<5)+(fn<<3)+lr;
                const int bo=nr*36+kk*8+lc;
                float bh0=BhS[bo], bh1=BhS[bo+4];
                float bl0=BlS[bo], bl1=BlS[bo+4];
#pragma unroll
                for(int fm=0;fm<4;fm++){
                    mma_tf32(acc[fm][fn], AH[fm], bh0, bh1);
                    mma_tf32(acc[fm][fn], AH[fm], bl0, bl1);
                    mma_tf32(acc[fm][fn], AL[fm], bh0, bh1);
                }
            }
        }
    }

    // epilogue: c0:(m,2lc) c1:(m,2lc+1) c2:(m+8,2lc) c3:(m+8,2lc+1)
#pragma unroll
    for(int fm=0;fm<4;fm++){
#pragma unroll
        for(int fn=0;fn<4;fn++){
            int m0=(wm<<6)+(fm<<4)+lr;
            int n0=(wn<<5)+(fn<<3)+(lc<<1);
            const float* a=acc[fm][fn];
#pragma unroll
            for(int r=0;r<4;r++){
                int m=m0+((r>>1)<<3);
                int n=n0+(r&1);
                if(n>=validPx) continue;
                int co=coBase+m;
                if(mode==0){
                    float v=a[r]+bias[co];
                    if(relu) v=fmaxf(v,0.f);
                    float h=tf32_hi(v);
                    size_t ad=((size_t)(cum+pixBase+n))*256+co;
                    outA[ad]=h; outB[ad]=tf32_hi(v-h);
                }else{
                    if(co<Cout)
                        outA[(size_t)co*HW + pixBase + n]=a[r]+bias[co];
                }
            }
        }
    }
}

// -------- tower layer kernel
__global__ __launch_bounds__(256,1)
void conv_tower_k(const float* __restrict__ Xh,const float* __restrict__ Xl,
                  const float* __restrict__ wCh,const float* __restrict__ wCl,
                  const float* __restrict__ wRh,const float* __restrict__ wRl,
                  const float* __restrict__ bC,const float* __restrict__ bR,
                  float* __restrict__ XhO,float* __restrict__ XlO,int first){
    extern __shared__ float smem[];
    const int bx=blockIdx.x;
    const int lvl=cb_lvl[bx], pixBase=cb_pix[bx];
    const int tower=blockIdx.y>>1, ct=blockIdx.y&1;
    const int b=blockIdx.z;
    const int W=cb_W[lvl],HW=cb_HW[lvl],lw=cb_LW[lvl],cum=cb_CUM[lvl];
    int inSlot = first ? b : (tower*4+b);
    int outSlot = tower*4+b;
    conv_mma(Xh+(size_t)inSlot*5440*256+(size_t)cum*256,
             Xl+(size_t)inSlot*5440*256+(size_t)cum*256,
             tower?wRh:wCh, tower?wRl:wCl, 2, ct, tower?bR:bC,
             W,HW,lw,pixBase, 0,256,1,
             XhO+(size_t)outSlot*5440*256, XlO+(size_t)outSlot*5440*256,
             cum, smem);
}

// -------- heads: y<6 cls (720ch), y==6 reg (36ch)
__global__ __launch_bounds__(256,1)
void conv_head_k(const float* __restrict__ Xh,const float* __restrict__ Xl,
                 const float* __restrict__ wCh,const float* __restrict__ wCl,
                 const float* __restrict__ wRh,const float* __restrict__ wRl,
                 const float* __restrict__ cob,const float* __restrict__ rob,
                 float* __restrict__ cls,float* __restrict__ reg){
    extern __shared__ float smem[];
    const int bx=blockIdx.x;
    const int lvl=cb_lvl[bx], pixBase=cb_pix[bx];
    const int y=blockIdx.y, b=blockIdx.z;
    const int W=cb_W[lvl],HW=cb_HW[lvl],lw=cb_LW[lvl],cum=cb_CUM[lvl];
    if(y<6){
        conv_mma(Xh+(size_t)b*5440*256+(size_t)cum*256,
                 Xl+(size_t)b*5440*256+(size_t)cum*256,
                 wCh, wCl, 6, y, cob,
                 W,HW,lw,pixBase, 1,720,0,
                 cls + (size_t)CLS_C*4*cum + (size_t)b*CLS_C*HW, 0, cum, smem);
    }else{
        conv_mma(Xh+(size_t)(4+b)*5440*256+(size_t)cum*256,
                 Xl+(size_t)(4+b)*5440*256+(size_t)cum*256,
                 wRh, wRl, 1, 0, rob,
                 W,HW,lw,pixBase, 1,36,0,
                 reg + (size_t)REG_C*4*cum + (size_t)b*REG_C*HW, 0, cum, smem);
    }
}

// ===================== selection (unchanged, validated) =====================
__device__ __forceinline__ float sigm(float v){ return 1.0f/(1.0f+expf(-v)); }
__device__ __forceinline__ bool is_cand(float v){
    if(v>-2.93f) return true;
    if(v<=-2.96f) return false;
    return sigm(v)>0.05f;
}

__global__ void zero_k(){
    int i=blockIdx.x*blockDim.x+threadIdx.x;
    if(i<16*65536) g_hist[i]=0;
    if(i<16) g_cnt[i]=0;
}

__global__ void hist_k(const float* __restrict__ cls){
    const int g=blockIdx.y, b=g>>2, lvl=g&3;
    const int HW=cb_HW[lvl], n=CLS_C*HW;
    const float* p=cls + (size_t)CLS_C*4*cb_CUM[lvl] + (size_t)b*n;
    for(int m=blockIdx.x*blockDim.x+threadIdx.x;m<n;m+=gridDim.x*blockDim.x){
        float v=p[m];
        if(is_cand(v)) atomicAdd(&g_hist[g*65536+(fkey(sigm(v))>>16)],1u);
    }
}

__global__ void scan_k(){
    const int g=blockIdx.x;
    __shared__ unsigned seg[256];
    const unsigned* h=&g_hist[g*65536];
    unsigned s=0; int base=threadIdx.x*256;
    for(int k=0;k<256;k++) s+=h[65535-(base+k)];
    seg[threadIdx.x]=s;
    __syncthreads();
    if(threadIdx.x==0){
        unsigned cum=0,thr=0;
        for(int sg=0;sg<256;sg++){
            if(cum+seg[sg]>=DPI){
                for(int k=0;k<256;k++){
                    cum+=h[65535-(sg*256+k)];
                    if(cum>=DPI){thr=65535-(sg*256+k);break;}
                }
                break;
            }
            cum+=seg[sg];
        }
        g_thr[g]=thr;
    }
}

__global__ void collect_k(const float* __restrict__ cls){
    const int g=blockIdx.y, b=g>>2, lvl=g&3;
    const int HW=cb_HW[lvl], n=CLS_C*HW;
    const unsigned thr=g_thr[g];
    const float* p=cls + (size_t)CLS_C*4*cb_CUM[lvl] + (size_t)b*n;
    for(int m=blockIdx.x*blockDim.x+threadIdx.x;m<n;m+=gridDim.x*blockDim.x){
        float v=p[m];
        if(!is_cand(v)) continue;
        unsigned u=fkey(sigm(v));
        if((u>>16)>=thr){
            int pos=atomicAdd(&g_cnt[g],1);
            if(pos<CAPB){
                int co=m/HW, pix=m-co*HW;
                unsigned nn=(unsigned)(pix*CLS_C+co);
                g_cand[(size_t)g*CAPB+pos]=((unsigned long long)u<<32)|(0xFFFFFFFFu-nn);
            }
        }
    }
}

__global__ __launch_bounds__(256)
void select_k(){
    const int g=blockIdx.x;
    int cnt=g_cnt[g]; if(cnt>CAPB) cnt=CAPB;
    unsigned long long* cand=&g_cand[(size_t)g*CAPB];
    __shared__ unsigned long long sc[4096];
    __shared__ unsigned long long wmax[8];
    __shared__ int wpos[8];
    const int tid=threadIdx.x, lane=tid&31, wid=tid>>5;
    const bool cached = cnt<=4096;
    if(cached) for(int i=tid;i<cnt;i+=256) sc[i]=cand[i];
    __syncthreads();
    unsigned long long* src = cached? sc : cand;
    for(int r=0;r<DPI;r++){
        unsigned long long mk=0ULL; int mp=-1;
        for(int i=tid;i<cnt;i+=256){
            unsigned long long k=src[i];
            if(k>mk){mk=k;mp=i;}
        }
#pragma unroll
        for(int off=16;off>0;off>>=1){
            unsigned long long ok=__shfl_down_sync(0xFFFFFFFFu,mk,off);
            int op=__shfl_down_sync(0xFFFFFFFFu,mp,off);
            if(ok>mk){mk=ok;mp=op;}
        }
        if(lane==0){wmax[wid]=mk;wpos[wid]=mp;}
        __syncthreads();
        if(tid==0){
            unsigned long long bk=wmax[0]; int bp=wpos[0];
#pragma unroll
            for(int w=1;w<8;w++) if(wmax[w]>bk){bk=wmax[w];bp=wpos[w];}
            g_sel[g*DPI+r]=bk;
            if(bp>=0) src[bp]=0ULL;
        }
        __syncthreads();
    }
}

__global__ void decode_k(const float* __restrict__ reg,
                         const int* __restrict__ ph,const int* __restrict__ pw){
    const int g=blockIdx.x, b=g>>2, lvl=g&3;
    const int r=threadIdx.x;
    if(r>=DPI) return;
    const int W=cb_W[lvl], HW=cb_HW[lvl];
    const float ih=(float)(*ph), iw=(float)(*pw);
    const int slot=b*400+lvl*DPI+r;
    unsigned long long k=g_sel[g*DPI+r];
    float* bx=&g_cbox[(size_t)slot*4];
    if(!k){ g_cscore[slot]=-1.f; g_clab[slot]=-1; bx[0]=bx[1]=bx[2]=bx[3]=0.f; return; }
    float sc=unfkey((unsigned)(k>>32));
    unsigned n=0xFFFFFFFFu-(unsigned)(k&0xFFFFFFFFu);
    int pix=(int)(n/CLS_C); int co=(int)(n-(unsigned)pix*CLS_C);
    int a=co/NC, c=co-a*NC;
    int hh=pix/W, ww=pix-hh*W;
    float size=c_sizes[lvl][a%3];
    float hr=sqrtf(c_ratios[a/3]);
    float wr=1.f/hr;
    float ws=wr*size, hs=hr*size;
    float st=(float)c_str[lvl];
    float sx=(float)ww*st, sy=(float)hh*st;
    float ax1=fminf(fmaxf(sx+rintf(-ws*0.5f),0.f),iw);
    float ay1=fminf(fmaxf(sy+rintf(-hs*0.5f),0.f),ih);
    float ax2=fminf(fmaxf(sx+rintf( ws*0.5f),0.f),iw);
    float ay2=fminf(fmaxf(sy+rintf( hs*0.5f),0.f),ih);
    float aw=ax2-ax1, ah=ay2-ay1;
    float cx=ax1+0.5f*aw, cy=ay1+0.5f*ah;
    const float* R=reg + (size_t)REG_C*4*cb_CUM[lvl] + (size_t)b*REG_C*HW;
    float dx=R[(a*4+0)*HW+pix];
    float dy=R[(a*4+1)*HW+pix];
    const float CLIPV=(float)4.135166556742356;
    float dw=fminf(R[(a*4+2)*HW+pix],CLIPV);
    float dh=fminf(R[(a*4+3)*HW+pix],CLIPV);
    float pcx=dx*aw+cx, pcy=dy*ah+cy;
    float pw_=expf(dw)*aw, ph_=expf(dh)*ah;
    bx[0]=fminf(fmaxf(pcx-0.5f*pw_,0.f),iw);
    bx[1]=fminf(fmaxf(pcy-0.5f*ph_,0.f),ih);
    bx[2]=fminf(fmaxf(pcx+0.5f*pw_,0.f),iw);
    bx[3]=fminf(fmaxf(pcy+0.5f*ph_,0.f),ih);
    g_cscore[slot]=sc;
    g_clab[slot]=c;
}

__global__ __launch_bounds__(512)
void final_k(float* __restrict__ out,const int* __restrict__ ph,const int* __restrict__ pw){
    int b=blockIdx.x, tid=threadIdx.x;
    __shared__ unsigned long long key[512];
    __shared__ float X1[512],Y1[512],X2[512],Y2[512],AR[512],SC[512];
    __shared__ float BX1[512],BY1[512],BX2[512],BY2[512];
    __shared__ int LB[512];
    __shared__ unsigned char KP[512];
    float ih=(float)(*ph), iw=(float)(*pw);
    float ob=fmaxf(ih,iw)+1.f;
    if(tid<400)
        key[tid]=((unsigned long long)fkey(g_cscore[b*400+tid])<<32)|(0xFFFFFFFFu-(unsigned)tid);
    else key[tid]=0ULL;
    __syncthreads();
    for(int k=2;k<=512;k<<=1)
        for(int j=k>>1;j>0;j>>=1){
            int ix=tid^j;
            if(ix>tid){
                unsigned long long a=key[tid],c=key[ix];
                if((a>c)==((tid&k)==0)){key[tid]=c;key[ix]=a;}
            }
            __syncthreads();
        }
    {
        unsigned long long k=key[511-tid];
        float sc=-1.f; int lb=-1; float b0=0,b1=0,b2=0,b3=0;
        if(k){
            unsigned i=0xFFFFFFFFu-(unsigned)(k&0xFFFFFFFFu);
            sc=unfkey((unsigned)(k>>32));
            lb=g_clab[b*400+i];
            const float* bp=&g_cbox[((size_t)b*400+i)*4];
            b0=bp[0];b1=bp[1];b2=bp[2];b3=bp[3];
        }
        float o=(float)lb*ob;
        BX1[tid]=b0;BY1[tid]=b1;BX2[tid]=b2;BY2[tid]=b3;
        X1[tid]=b0+o;Y1[tid]=b1+o;X2[tid]=b2+o;Y2[tid]=b3+o;
        SC[tid]=sc;LB[tid]=lb;
        AR[tid]=(X2[tid]-X1[tid])*(Y2[tid]-Y1[tid]);
        KP[tid]=(sc>0.05f)?1:0;
    }
    __syncthreads();
    for(int i=0;i<400;i++){
        if(KP[i]&&tid>i&&tid<400&&KP[tid]){
            float w=fmaxf(fminf(X2[i],X2[tid])-fmaxf(X1[i],X1[tid]),0.f);
            float h=fmaxf(fminf(Y2[i],Y2[tid])-fmaxf(Y1[i],Y1[tid]),0.f);
            float it=w*h;
            float iou=it/(AR[i]+AR[tid]-it+1e-9f);
            if(iou>0.5f) KP[tid]=0;
        }
        __syncthreads();
    }
    if(tid==0){
        int o=0;
        for(int r=0;r<400&&o<DPI;r++) if(KP[r]){
            out[(b*DPI+o)*4+0]=BX1[r]; out[(b*DPI+o)*4+1]=BY1[r];
            out[(b*DPI+o)*4+2]=BX2[r]; out[(b*DPI+o)*4+3]=BY2[r];
            out[1600+b*DPI+o]=SC[r];   out[2000+b*DPI+o]=(float)LB[r];
            o++;
        }
        for(;o<DPI;o++){
            out[(b*DPI+o)*4+0]=0.f; out[(b*DPI+o)*4+1]=0.f;
            out[(b*DPI+o)*4+2]=0.f; out[(b*DPI+o)*4+3]=0.f;
            out[1600+b*DPI+o]=0.f;  out[2000+b*DPI+o]=-1.f;
        }
    }
}

extern "C" void kernel_launch(void* const* d_in, const int* in_sizes, int n_in,
                              void* d_out, int out_size){
    const float* f0=(const float*)d_in[0];
    const float* f1=(const float*)d_in[1];
    const float* f2=(const float*)d_in[2];
    const float* f3=(const float*)d_in[3];
    const float* ctw=(const float*)d_in[4];
    const float* ctb=(const float*)d_in[5];
    const float* cow=(const float*)d_in[6];
    const float* cob=(const float*)d_in[7];
    const float* rtw=(const float*)d_in[8];
    const float* rtb=(const float*)d_in[9];
    const float* row_=(const float*)d_in[10];
    const float* rob=(const float*)d_in[11];
    const int* ph=(const int*)d_in[12];
    const int* pw=(const int*)d_in[13];

    float *xh0,*xl0,*xh1,*xl1,*cls,*reg,*wh,*wl;
    cudaGetSymbolAddress((void**)&xh0,g_xh0);
    cudaGetSymbolAddress((void**)&xl0,g_xl0);
    cudaGetSymbolAddress((void**)&xh1,g_xh1);
    cudaGetSymbolAddress((void**)&xl1,g_xl1);
    cudaGetSymbolAddress((void**)&cls,g_cls);
    cudaGetSymbolAddress((void**)&reg,g_reg);
    cudaGetSymbolAddress((void**)&wh,g_wth);
    cudaGetSymbolAddress((void**)&wl,g_wtl);

    cudaFuncSetAttribute(conv_tower_k, cudaFuncAttributeMaxDynamicSharedMemorySize, SMEMBYTES);
    cudaFuncSetAttribute(conv_head_k,  cudaFuncAttributeMaxDynamicSharedMemorySize, SMEMBYTES);

    prep_k<<<2048,256>>>(f0,f1,f2,f3,xh0,xl0);
    wtrans_k<<<2048,256>>>(ctw, wh+OFF_CLS_TW, wl+OFF_CLS_TW, 256,2,4);
    wtrans_k<<<2048,256>>>(rtw, wh+OFF_REG_TW, wl+OFF_REG_TW, 256,2,4);
    wtrans_k<<<2048,256>>>(cow, wh+OFF_CLS_OW, wl+OFF_CLS_OW, 720,6,1);
    wtrans_k<<<1024,256>>>(row_, wh+OFF_REG_OW, wl+OFF_REG_OW, 36,1,1);

    const size_t LSZ = 589824;
    conv_tower_k<<<dim3(43,4,BATCH),256,SMEMBYTES>>>(xh0,xl0,
        wh+OFF_CLS_TW+0*LSZ, wl+OFF_CLS_TW+0*LSZ,
        wh+OFF_REG_TW+0*LSZ, wl+OFF_REG_TW+0*LSZ, ctb+0,  rtb+0,  xh1,xl1, 1);
    conv_tower_k<<<dim3(43,4,BATCH),256,SMEMBYTES>>>(xh1,xl1,
        wh+OFF_CLS_TW+1*LSZ, wl+OFF_CLS_TW+1*LSZ,
        wh+OFF_REG_TW+1*LSZ, wl+OFF_REG_TW+1*LSZ, ctb+256,rtb+256,xh0,xl0, 0);
    conv_tower_k<<<dim3(43,4,BATCH),256,SMEMBYTES>>>(xh0,xl0,
        wh+OFF_CLS_TW+2*LSZ, wl+OFF_CLS_TW+2*LSZ,
        wh+OFF_REG_TW+2*LSZ, wl+OFF_REG_TW+2*LSZ, ctb+512,rtb+512,xh1,xl1, 0);
    conv_tower_k<<<dim3(43,4,BATCH),256,SMEMBYTES>>>(xh1,xl1,
        wh+OFF_CLS_TW+3*LSZ, wl+OFF_CLS_TW+3*LSZ,
        wh+OFF_REG_TW+3*LSZ, wl+OFF_REG_TW+3*LSZ, ctb+768,rtb+768,xh0,xl0, 0);
    conv_head_k<<<dim3(43,7,BATCH),256,SMEMBYTES>>>(xh0,xl0,
        wh+OFF_CLS_OW, wl+OFF_CLS_OW, wh+OFF_REG_OW, wl+OFF_REG_OW,
        cob, rob, cls, reg);

    zero_k<<<4096,256>>>();
    hist_k<<<dim3(256,16),256>>>(cls);
    scan_k<<<16,256>>>();
    collect_k<<<dim3(256,16),256>>>(cls);
    select_k<<<16,256>>>();
    decode_k<<<16,128>>>(reg,ph,pw);
    final_k<<<BATCH,512>>>((float*)d_out,ph,pw);
}

// round 12
// speedup vs baseline: 1.2314x; 1.0626x over previous
#include <cuda_runtime.h>
#include <math.h>

#define NC 80
#define CLS_C 720
#define REG_C 36
#define DPI 100
#define BATCH 4
#define CAPB 131072

// -------- level tables --------
__constant__ int cb_W[4]   = {64,32,16,8};
__constant__ int cb_HW[4]  = {4096,1024,256,64};
__constant__ int cb_LW[4]  = {6,5,4,3};
__constant__ int cb_CUM[4] = {0,4096,5120,5376};
__constant__ int cb_lvl[43] = {0,0,0,0,0,0,0,0,0,0,0,0,0,0,0,0,
                               0,0,0,0,0,0,0,0,0,0,0,0,0,0,0,0,
                               1,1,1,1,1,1,1,1, 2,2, 3};
__constant__ int cb_pix[43] = {0,128,256,384,512,640,768,896,1024,1152,1280,1408,
                               1536,1664,1792,1920,2048,2176,2304,2432,2560,2688,
                               2816,2944,3072,3200,3328,3456,3584,3712,3840,3968,
                               0,128,256,384,512,640,768,896, 0,128, 0};

__device__ __constant__ float c_sizes[4][3] = {
    {32.f,40.f,50.f},{64.f,80.f,101.f},{128.f,161.f,203.f},{256.f,322.f,406.f}};
__device__ __constant__ float c_ratios[3] = {0.5f,1.0f,2.0f};
__device__ __constant__ int   c_str[4] = {8,16,32,64};

#define OFF_CLS_TW 0
#define OFF_REG_TW 2359296
#define OFF_CLS_OW 4718592
#define OFF_REG_OW 6488064
#define WT_TOTAL   6782976

// -------- scratch --------
__device__ __align__(16) float g_x0[(size_t)8*5440*256];
__device__ __align__(16) float g_x1[(size_t)8*5440*256];
__device__ __align__(16) float g_wt[WT_TOTAL];
__device__ __align__(16) float g_cls[BATCH*CLS_C*5440];
__device__ __align__(16) float g_reg[BATCH*REG_C*5440];
__device__ unsigned g_hist[16*65536];
__device__ unsigned g_thr[16];
__device__ int      g_cnt[16];
__device__ unsigned long long g_cand[(size_t)16*CAPB];
__device__ unsigned long long g_sel[16*DPI];
__device__ float g_cbox[BATCH*400*4];
__device__ float g_cscore[BATCH*400];
__device__ int   g_clab[BATCH*400];

__device__ __forceinline__ unsigned fkey(float f){
    unsigned b=__float_as_uint(f);
    return b ^ ((b>>31) ? 0xFFFFFFFFu : 0x80000000u);
}
__device__ __forceinline__ float unfkey(unsigned u){
    unsigned b=u ^ ((u>>31) ? 0x80000000u : 0xFFFFFFFFu);
    return __uint_as_float(b);
}
__device__ __forceinline__ float tf32_hi(float x){
    unsigned r;
    asm("cvt.rna.tf32.f32 %0, %1;" : "=r"(r) : "f"(x));
    return __uint_as_float(r);
}
__device__ __forceinline__ void mma_tf32(float* c,
        float a0,float a1,float a2,float a3, float b0, float b1){
    asm("mma.sync.aligned.m16n8k8.row.col.f32.tf32.tf32.f32 "
        "{%0,%1,%2,%3},{%4,%5,%6,%7},{%8,%9},{%0,%1,%2,%3};"
        : "+f"(c[0]),"+f"(c[1]),"+f"(c[2]),"+f"(c[3])
        : "r"(__float_as_uint(a0)),"r"(__float_as_uint(a1)),
          "r"(__float_as_uint(a2)),"r"(__float_as_uint(a3)),
          "r"(__float_as_uint(b0)),"r"(__float_as_uint(b1)));
}
__device__ __forceinline__ unsigned smem_u32(const void* p){
    unsigned a;
    asm("{ .reg .u64 t; cvta.to.shared.u64 t, %1; cvt.u32.u64 %0, t; }"
        : "=r"(a) : "l"(p));
    return a;
}
__device__ __forceinline__ void cp16(unsigned dst, const void* src, int sz){
    asm volatile("cp.async.cg.shared.global [%0], [%1], 16, %2;"
                 :: "r"(dst), "l"(src), "r"(sz));
}
#define CP_COMMIT() asm volatile("cp.async.commit_group;" ::: "memory")
#define CP_WAIT0()  asm volatile("cp.async.wait_group 0;" ::: "memory")
#define CP_WAIT1()  asm volatile("cp.async.wait_group 1;" ::: "memory")
#define CP_WAIT2()  asm volatile("cp.async.wait_group 2;" ::: "memory")

// -------- prep: transpose fp32 [b][ci][pix] -> [b][pixG][ci]
__global__ void prep_k(const float* __restrict__ f0,const float* __restrict__ f1,
                       const float* __restrict__ f2,const float* __restrict__ f3,
                       float* __restrict__ out){
    size_t total=(size_t)4*5440*256;
    for(size_t e=(size_t)blockIdx.x*blockDim.x+threadIdx.x;e<total;
        e+=(size_t)gridDim.x*blockDim.x){
        int ci=(int)(e&255);
        int pixG=(int)((e>>8)%5440);
        int b=(int)(e/(5440*256));
        int lvl = pixG<4096?0 : pixG<5120?1 : pixG<5376?2 : 3;
        int cum = lvl==0?0 : lvl==1?4096 : lvl==2?5120 : 5376;
        int HW  = lvl==0?4096 : lvl==1?1024 : lvl==2?256 : 64;
        const float* f = lvl==0?f0 : lvl==1?f1 : lvl==2?f2 : f3;
        out[e] = f[((size_t)b*256+ci)*HW + (pixG-cum)];
    }
}

// -------- weight transform into FRAGMENT-MAJOR fp32 (unsplit)
// per (layer,kpos,coTile128): 8 chunk-blocks of 4096 floats; within:
// off = (((kk*2+wm)*4+fm)*32 + lane)*4 + v
__global__ void wtrans_k(const float* __restrict__ src,
                         float* __restrict__ dst,
                         int Cout,int nTiles,int nL){
    size_t total=(size_t)nL*9*nTiles*32768;
    for(size_t e=(size_t)blockIdx.x*blockDim.x+threadIdx.x;e<total;
        e+=(size_t)gridDim.x*blockDim.x){
        int off=(int)(e&4095);
        int cchunk=(int)((e>>12)&7);
        size_t t=e>>15;
        int ct=(int)(t%nTiles); t/=nTiles;
        int kpos=(int)(t%9); int layer=(int)(t/9);
        int v=off&3, lane=(off>>2)&31, fm=(off>>7)&3, wm=(off>>9)&1, kk=(off>>10)&3;
        int lr=lane>>2, lc=lane&3;
        int co=ct*128 + wm*64 + fm*16 + (v&1)*8 + lr;
        int k =cchunk*32 + kk*8 + (v>>1)*4 + lc;
        float val=0.f;
        if(co<Cout) val=src[(((size_t)layer*Cout+co)*256+k)*9+kpos];
        dst[e]=val;
    }
}

// ===================== 3xTF32 mma conv core (4-stage cp.async, on-fly split)
#define STAGEF 8704                   // A 4096 + B 4608 floats
#define SMEMBYTES (4*STAGEF*4)        // 139264

__device__ void conv_mma(
    const float* __restrict__ X,
    const float* __restrict__ Wf,
    int nTiles, int ct, const float* __restrict__ bias,
    int W, int HW, int lw, int pixBase,
    int mode, int Cout, int relu,
    float* __restrict__ outA,
    int cum, float* smem)
{
    const int tid=threadIdx.x;
    const int lane=tid&31, wid=tid>>5;
    const int wm=wid&1, wn=wid>>1;
    const int lr=lane>>2, lc=lane&3;
    const int coBase=ct*128;

    int validPx = HW - pixBase; if(validPx>128) validPx=128;

    const int srow=tid>>1, half=tid&1;
    const int q=pixBase+srow;
    const bool rowv = srow<validPx;
    const int hh=q>>lw, ww=q&(W-1);

    const unsigned sb = smem_u32(smem);

    float acc[4][4][4];
#pragma unroll
    for(int i=0;i<4;i++)
#pragma unroll
        for(int j=0;j<4;j++)
#pragma unroll
            for(int r=0;r<4;r++) acc[i][j][r]=0.f;

    auto stage=[&](int ch,int s){
        const int kpos=ch>>3, cc=ch&7;
        const unsigned base = sb + (unsigned)(s*STAGEF*4);
        // A (fragment-major fp32)
        const float* aw=Wf + ((size_t)(kpos*nTiles+ct))*32768 + cc*4096 + tid*16;
#pragma unroll
        for(int i=0;i<4;i++)
            cp16(base + (tid*16+i*4)*4, aw+i*4, 16);
        // B: X rows with halo, zero-fill OOB
        const int dh=kpos/3-1, dw=kpos-(kpos/3)*3-1;
        const int hs=hh+dh, ws=ww+dw;
        const bool ok = rowv && (unsigned)hs<(unsigned)W && (unsigned)ws<(unsigned)W;
        const size_t xoff = ok ? ((size_t)(hs*W+ws)*256) : 0;
        const int sz = ok?16:0;
        const float* xr = X + xoff + cc*32 + half*16;
        const unsigned bh = base + (4096 + srow*36 + half*16)*4;
#pragma unroll
        for(int i=0;i<4;i++)
            cp16(bh + i*16, xr+i*4, sz);
    };

    stage(0,0); CP_COMMIT();
    stage(1,1); CP_COMMIT();
    stage(2,2); CP_COMMIT();

    for(int ch=0;ch<72;ch++){
        const int s=ch&3;
        if(ch<70) CP_WAIT2();
        else if(ch==70) CP_WAIT1();
        else CP_WAIT0();
        __syncthreads();
        if(ch+3<72){ stage(ch+3,(ch+3)&3); CP_COMMIT(); }
        float* S = smem + s*STAGEF;
        float* AS=S; float* BS=S+4096;
#pragma unroll
        for(int kk=0;kk<4;kk++){
            float4 ahF[4]; float ahh[4][4], ahl[4][4];
#pragma unroll
            for(int fm=0;fm<4;fm++){
                const int fo=((kk*2+wm)*4+fm)*128 + lane*4;
                ahF[fm]=*(const float4*)&AS[fo];
                ahh[fm][0]=tf32_hi(ahF[fm].x); ahl[fm][0]=tf32_hi(ahF[fm].x-ahh[fm][0]);
                ahh[fm][1]=tf32_hi(ahF[fm].y); ahl[fm][1]=tf32_hi(ahF[fm].y-ahh[fm][1]);
                ahh[fm][2]=tf32_hi(ahF[fm].z); ahl[fm][2]=tf32_hi(ahF[fm].z-ahh[fm][2]);
                ahh[fm][3]=tf32_hi(ahF[fm].w); ahl[fm][3]=tf32_hi(ahF[fm].w-ahh[fm][3]);
            }
#pragma unroll
            for(int fn=0;fn<4;fn++){
                const int nr=(wn<<5)+(fn<<3)+lr;
                const int bo=nr*36+kk*8+lc;
                float b0=BS[bo], b1=BS[bo+4];
                float bh0=tf32_hi(b0), bl0=tf32_hi(b0-bh0);
                float bh1=tf32_hi(b1), bl1=tf32_hi(b1-bh1);
#pragma unroll
                for(int fm=0;fm<4;fm++){
                    mma_tf32(acc[fm][fn], ahh[fm][0],ahh[fm][1],ahh[fm][2],ahh[fm][3], bh0, bh1);
                    mma_tf32(acc[fm][fn], ahh[fm][0],ahh[fm][1],ahh[fm][2],ahh[fm][3], bl0, bl1);
                    mma_tf32(acc[fm][fn], ahl[fm][0],ahl[fm][1],ahl[fm][2],ahl[fm][3], bh0, bh1);
                }
            }
        }
    }

    // epilogue: c0:(m,2lc) c1:(m,2lc+1) c2:(m+8,2lc) c3:(m+8,2lc+1)
#pragma unroll
    for(int fm=0;fm<4;fm++){
#pragma unroll
        for(int fn=0;fn<4;fn++){
            int m0=(wm<<6)+(fm<<4)+lr;
            int n0=(wn<<5)+(fn<<3)+(lc<<1);
            const float* a=acc[fm][fn];
#pragma unroll
            for(int r=0;r<4;r++){
                int m=m0+((r>>1)<<3);
                int n=n0+(r&1);
                if(n>=validPx) continue;
                int co=coBase+m;
                if(mode==0){
                    float v=a[r]+bias[co];
                    if(relu) v=fmaxf(v,0.f);
                    outA[((size_t)(cum+pixBase+n))*256+co]=v;
                }else{
                    if(co<Cout)
                        outA[(size_t)co*HW + pixBase + n]=a[r]+bias[co];
                }
            }
        }
    }
}

// -------- tower layer kernel
__global__ __launch_bounds__(256,1)
void conv_tower_k(const float* __restrict__ Xin,
                  const float* __restrict__ wC,const float* __restrict__ wR,
                  const float* __restrict__ bC,const float* __restrict__ bR,
                  float* __restrict__ Xout,int first){
    extern __shared__ float smem[];
    const int bx=blockIdx.x;
    const int lvl=cb_lvl[bx], pixBase=cb_pix[bx];
    const int tower=blockIdx.y>>1, ct=blockIdx.y&1;
    const int b=blockIdx.z;
    const int W=cb_W[lvl],HW=cb_HW[lvl],lw=cb_LW[lvl],cum=cb_CUM[lvl];
    int inSlot = first ? b : (tower*4+b);
    int outSlot = tower*4+b;
    conv_mma(Xin+(size_t)inSlot*5440*256+(size_t)cum*256,
             tower?wR:wC, 2, ct, tower?bR:bC,
             W,HW,lw,pixBase, 0,256,1,
             Xout+(size_t)outSlot*5440*256, cum, smem);
}

// -------- heads: y<6 cls (720ch), y==6 reg (36ch)
__global__ __launch_bounds__(256,1)
void conv_head_k(const float* __restrict__ Xin,
                 const float* __restrict__ wC,const float* __restrict__ wR,
                 const float* __restrict__ cob,const float* __restrict__ rob,
                 float* __restrict__ cls,float* __restrict__ reg){
    extern __shared__ float smem[];
    const int bx=blockIdx.x;
    const int lvl=cb_lvl[bx], pixBase=cb_pix[bx];
    const int y=blockIdx.y, b=blockIdx.z;
    const int W=cb_W[lvl],HW=cb_HW[lvl],lw=cb_LW[lvl],cum=cb_CUM[lvl];
    if(y<6){
        conv_mma(Xin+(size_t)b*5440*256+(size_t)cum*256,
                 wC, 6, y, cob,
                 W,HW,lw,pixBase, 1,720,0,
                 cls + (size_t)CLS_C*4*cum + (size_t)b*CLS_C*HW, cum, smem);
    }else{
        conv_mma(Xin+(size_t)(4+b)*5440*256+(size_t)cum*256,
                 wR, 1, 0, rob,
                 W,HW,lw,pixBase, 1,36,0,
                 reg + (size_t)REG_C*4*cum + (size_t)b*REG_C*HW, cum, smem);
    }
}

// ===================== selection (unchanged, validated) =====================
__device__ __forceinline__ float sigm(float v){ return 1.0f/(1.0f+expf(-v)); }
__device__ __forceinline__ bool is_cand(float v){
    if(v>-2.93f) return true;
    if(v<=-2.96f) return false;
    return sigm(v)>0.05f;
}

__global__ void zero_k(){
    int i=blockIdx.x*blockDim.x+threadIdx.x;
    if(i<16*65536) g_hist[i]=0;
    if(i<16) g_cnt[i]=0;
}

__global__ void hist_k(const float* __restrict__ cls){
    const int g=blockIdx.y, b=g>>2, lvl=g&3;
    const int HW=cb_HW[lvl], n=CLS_C*HW;
    const float* p=cls + (size_t)CLS_C*4*cb_CUM[lvl] + (size_t)b*n;
    for(int m=blockIdx.x*blockDim.x+threadIdx.x;m<n;m+=gridDim.x*blockDim.x){
        float v=p[m];
        if(is_cand(v)) atomicAdd(&g_hist[g*65536+(fkey(sigm(v))>>16)],1u);
    }
}

__global__ void scan_k(){
    const int g=blockIdx.x;
    __shared__ unsigned seg[256];
    const unsigned* h=&g_hist[g*65536];
    unsigned s=0; int base=threadIdx.x*256;
    for(int k=0;k<256;k++) s+=h[65535-(base+k)];
    seg[threadIdx.x]=s;
    __syncthreads();
    if(threadIdx.x==0){
        unsigned cum=0,thr=0;
        for(int sg=0;sg<256;sg++){
            if(cum+seg[sg]>=DPI){
                for(int k=0;k<256;k++){
                    cum+=h[65535-(sg*256+k)];
                    if(cum>=DPI){thr=65535-(sg*256+k);break;}
                }
                break;
            }
            cum+=seg[sg];
        }
        g_thr[g]=thr;
    }
}

__global__ void collect_k(const float* __restrict__ cls){
    const int g=blockIdx.y, b=g>>2, lvl=g&3;
    const int HW=cb_HW[lvl], n=CLS_C*HW;
    const unsigned thr=g_thr[g];
    const float* p=cls + (size_t)CLS_C*4*cb_CUM[lvl] + (size_t)b*n;
    for(int m=blockIdx.x*blockDim.x+threadIdx.x;m<n;m+=gridDim.x*blockDim.x){
        float v=p[m];
        if(!is_cand(v)) continue;
        unsigned u=fkey(sigm(v));
        if((u>>16)>=thr){
            int pos=atomicAdd(&g_cnt[g],1);
            if(pos<CAPB){
                int co=m/HW, pix=m-co*HW;
                unsigned nn=(unsigned)(pix*CLS_C+co);
                g_cand[(size_t)g*CAPB+pos]=((unsigned long long)u<<32)|(0xFFFFFFFFu-nn);
            }
        }
    }
}

__global__ __launch_bounds__(256)
void select_k(){
    const int g=blockIdx.x;
    int cnt=g_cnt[g]; if(cnt>CAPB) cnt=CAPB;
    unsigned long long* cand=&g_cand[(size_t)g*CAPB];
    __shared__ unsigned long long sc[4096];
    __shared__ unsigned long long wmax[8];
    __shared__ int wpos[8];
    const int tid=threadIdx.x, lane=tid&31, wid=tid>>5;
    const bool cached = cnt<=4096;
    if(cached) for(int i=tid;i<cnt;i+=256) sc[i]=cand[i];
    __syncthreads();
    unsigned long long* src = cached? sc : cand;
    for(int r=0;r<DPI;r++){
        unsigned long long mk=0ULL; int mp=-1;
        for(int i=tid;i<cnt;i+=256){
            unsigned long long k=src[i];
            if(k>mk){mk=k;mp=i;}
        }
#pragma unroll
        for(int off=16;off>0;off>>=1){
            unsigned long long ok=__shfl_down_sync(0xFFFFFFFFu,mk,off);
            int op=__shfl_down_sync(0xFFFFFFFFu,mp,off);
            if(ok>mk){mk=ok;mp=op;}
        }
        if(lane==0){wmax[wid]=mk;wpos[wid]=mp;}
        __syncthreads();
        if(tid==0){
            unsigned long long bk=wmax[0]; int bp=wpos[0];
#pragma unroll
            for(int w=1;w<8;w++) if(wmax[w]>bk){bk=wmax[w];bp=wpos[w];}
            g_sel[g*DPI+r]=bk;
            if(bp>=0) src[bp]=0ULL;
        }
        __syncthreads();
    }
}

__global__ void decode_k(const float* __restrict__ reg,
                         const int* __restrict__ ph,const int* __restrict__ pw){
    const int g=blockIdx.x, b=g>>2, lvl=g&3;
    const int r=threadIdx.x;
    if(r>=DPI) return;
    const int W=cb_W[lvl], HW=cb_HW[lvl];
    const float ih=(float)(*ph), iw=(float)(*pw);
    const int slot=b*400+lvl*DPI+r;
    unsigned long long k=g_sel[g*DPI+r];
    float* bx=&g_cbox[(size_t)slot*4];
    if(!k){ g_cscore[slot]=-1.f; g_clab[slot]=-1; bx[0]=bx[1]=bx[2]=bx[3]=0.f; return; }
    float sc=unfkey((unsigned)(k>>32));
    unsigned n=0xFFFFFFFFu-(unsigned)(k&0xFFFFFFFFu);
    int pix=(int)(n/CLS_C); int co=(int)(n-(unsigned)pix*CLS_C);
    int a=co/NC, c=co-a*NC;
    int hh=pix/W, ww=pix-hh*W;
    float size=c_sizes[lvl][a%3];
    float hr=sqrtf(c_ratios[a/3]);
    float wr=1.f/hr;
    float ws=wr*size, hs=hr*size;
    float st=(float)c_str[lvl];
    float sx=(float)ww*st, sy=(float)hh*st;
    float ax1=fminf(fmaxf(sx+rintf(-ws*0.5f),0.f),iw);
    float ay1=fminf(fmaxf(sy+rintf(-hs*0.5f),0.f),ih);
    float ax2=fminf(fmaxf(sx+rintf( ws*0.5f),0.f),iw);
    float ay2=fminf(fmaxf(sy+rintf( hs*0.5f),0.f),ih);
    float aw=ax2-ax1, ah=ay2-ay1;
    float cx=ax1+0.5f*aw, cy=ay1+0.5f*ah;
    const float* R=reg + (size_t)REG_C*4*cb_CUM[lvl] + (size_t)b*REG_C*HW;
    float dx=R[(a*4+0)*HW+pix];
    float dy=R[(a*4+1)*HW+pix];
    const float CLIPV=(float)4.135166556742356;
    float dw=fminf(R[(a*4+2)*HW+pix],CLIPV);
    float dh=fminf(R[(a*4+3)*HW+pix],CLIPV);
    float pcx=dx*aw+cx, pcy=dy*ah+cy;
    float pw_=expf(dw)*aw, ph_=expf(dh)*ah;
    bx[0]=fminf(fmaxf(pcx-0.5f*pw_,0.f),iw);
    bx[1]=fminf(fmaxf(pcy-0.5f*ph_,0.f),ih);
    bx[2]=fminf(fmaxf(pcx+0.5f*pw_,0.f),iw);
    bx[3]=fminf(fmaxf(pcy+0.5f*ph_,0.f),ih);
    g_cscore[slot]=sc;
    g_clab[slot]=c;
}

__global__ __launch_bounds__(512)
void final_k(float* __restrict__ out,const int* __restrict__ ph,const int* __restrict__ pw){
    int b=blockIdx.x, tid=threadIdx.x;
    __shared__ unsigned long long key[512];
    __shared__ float X1[512],Y1[512],X2[512],Y2[512],AR[512],SC[512];
    __shared__ float BX1[512],BY1[512],BX2[512],BY2[512];
    __shared__ int LB[512];
    __shared__ unsigned char KP[512];
    float ih=(float)(*ph), iw=(float)(*pw);
    float ob=fmaxf(ih,iw)+1.f;
    if(tid<400)
        key[tid]=((unsigned long long)fkey(g_cscore[b*400+tid])<<32)|(0xFFFFFFFFu-(unsigned)tid);
    else key[tid]=0ULL;
    __syncthreads();
    for(int k=2;k<=512;k<<=1)
        for(int j=k>>1;j>0;j>>=1){
            int ix=tid^j;
            if(ix>tid){
                unsigned long long a=key[tid],c=key[ix];
                if((a>c)==((tid&k)==0)){key[tid]=c;key[ix]=a;}
            }
            __syncthreads();
        }
    {
        unsigned long long k=key[511-tid];
        float sc=-1.f; int lb=-1; float b0=0,b1=0,b2=0,b3=0;
        if(k){
            unsigned i=0xFFFFFFFFu-(unsigned)(k&0xFFFFFFFFu);
            sc=unfkey((unsigned)(k>>32));
            lb=g_clab[b*400+i];
            const float* bp=&g_cbox[((size_t)b*400+i)*4];
            b0=bp[0];b1=bp[1];b2=bp[2];b3=bp[3];
        }
        float o=(float)lb*ob;
        BX1[tid]=b0;BY1[tid]=b1;BX2[tid]=b2;BY2[tid]=b3;
        X1[tid]=b0+o;Y1[tid]=b1+o;X2[tid]=b2+o;Y2[tid]=b3+o;
        SC[tid]=sc;LB[tid]=lb;
        AR[tid]=(X2[tid]-X1[tid])*(Y2[tid]-Y1[tid]);
        KP[tid]=(sc>0.05f)?1:0;
    }
    __syncthreads();
    for(int i=0;i<400;i++){
        if(KP[i]&&tid>i&&tid<400&&KP[tid]){
            float w=fmaxf(fminf(X2[i],X2[tid])-fmaxf(X1[i],X1[tid]),0.f);
            float h=fmaxf(fminf(Y2[i],Y2[tid])-fmaxf(Y1[i],Y1[tid]),0.f);
            float it=w*h;
            float iou=it/(AR[i]+AR[tid]-it+1e-9f);
            if(iou>0.5f) KP[tid]=0;
        }
        __syncthreads();
    }
    if(tid==0){
        int o=0;
        for(int r=0;r<400&&o<DPI;r++) if(KP[r]){
            out[(b*DPI+o)*4+0]=BX1[r]; out[(b*DPI+o)*4+1]=BY1[r];
            out[(b*DPI+o)*4+2]=BX2[r]; out[(b*DPI+o)*4+3]=BY2[r];
            out[1600+b*DPI+o]=SC[r];   out[2000+b*DPI+o]=(float)LB[r];
            o++;
        }
        for(;o<DPI;o++){
            out[(b*DPI+o)*4+0]=0.f; out[(b*DPI+o)*4+1]=0.f;
            out[(b*DPI+o)*4+2]=0.f; out[(b*DPI+o)*4+3]=0.f;
            out[1600+b*DPI+o]=0.f;  out[2000+b*DPI+o]=-1.f;
        }
    }
}

extern "C" void kernel_launch(void* const* d_in, const int* in_sizes, int n_in,
                              void* d_out, int out_size){
    const float* f0=(const float*)d_in[0];
    const float* f1=(const float*)d_in[1];
    const float* f2=(const float*)d_in[2];
    const float* f3=(const float*)d_in[3];
    const float* ctw=(const float*)d_in[4];
    const float* ctb=(const float*)d_in[5];
    const float* cow=(const float*)d_in[6];
    const float* cob=(const float*)d_in[7];
    const float* rtw=(const float*)d_in[8];
    const float* rtb=(const float*)d_in[9];
    const float* row_=(const float*)d_in[10];
    const float* rob=(const float*)d_in[11];
    const int* ph=(const int*)d_in[12];
    const int* pw=(const int*)d_in[13];

    float *x0,*x1,*cls,*reg,*wt;
    cudaGetSymbolAddress((void**)&x0,g_x0);
    cudaGetSymbolAddress((void**)&x1,g_x1);
    cudaGetSymbolAddress((void**)&cls,g_cls);
    cudaGetSymbolAddress((void**)&reg,g_reg);
    cudaGetSymbolAddress((void**)&wt,g_wt);

    cudaFuncSetAttribute(conv_tower_k, cudaFuncAttributeMaxDynamicSharedMemorySize, SMEMBYTES);
    cudaFuncSetAttribute(conv_head_k,  cudaFuncAttributeMaxDynamicSharedMemorySize, SMEMBYTES);

    prep_k<<<2048,256>>>(f0,f1,f2,f3,x0);
    wtrans_k<<<2048,256>>>(ctw, wt+OFF_CLS_TW, 256,2,4);
    wtrans_k<<<2048,256>>>(rtw, wt+OFF_REG_TW, 256,2,4);
    wtrans_k<<<2048,256>>>(cow, wt+OFF_CLS_OW, 720,6,1);
    wtrans_k<<<1024,256>>>(row_, wt+OFF_REG_OW, 36,1,1);

    const size_t LSZ = 589824;
    conv_tower_k<<<dim3(43,4,BATCH),256,SMEMBYTES>>>(x0,
        wt+OFF_CLS_TW+0*LSZ, wt+OFF_REG_TW+0*LSZ, ctb+0,  rtb+0,  x1, 1);
    conv_tower_k<<<dim3(43,4,BATCH),256,SMEMBYTES>>>(x1,
        wt+OFF_CLS_TW+1*LSZ, wt+OFF_REG_TW+1*LSZ, ctb+256,rtb+256,x0, 0);
    conv_tower_k<<<dim3(43,4,BATCH),256,SMEMBYTES>>>(x0,
        wt+OFF_CLS_TW+2*LSZ, wt+OFF_REG_TW+2*LSZ, ctb+512,rtb+512,x1, 0);
    conv_tower_k<<<dim3(43,4,BATCH),256,SMEMBYTES>>>(x1,
        wt+OFF_CLS_TW+3*LSZ, wt+OFF_REG_TW+3*LSZ, ctb+768,rtb+768,x0, 0);
    conv_head_k<<<dim3(43,7,BATCH),256,SMEMBYTES>>>(x0,
        wt+OFF_CLS_OW, wt+OFF_REG_OW, cob, rob, cls, reg);

    zero_k<<<4096,256>>>();
    hist_k<<<dim3(256,16),256>>>(cls);
    scan_k<<<16,256>>>();
    collect_k<<<dim3(256,16),256>>>(cls);
    select_k<<<16,256>>>();
    decode_k<<<16,128>>>(reg,ph,pw);
    final_k<<<BATCH,512>>>((float*)d_out,ph,pw);
}

// round 15
// speedup vs baseline: 2.1286x; 1.7286x over previous
#include <cuda_runtime.h>
#include <cuda_fp16.h>
#include <math.h>

#define NC 80
#define CLS_C 720
#define REG_C 36
#define DPI 100
#define BATCH 4
#define CAPB 131072

__constant__ int cb_W[4]   = {64,32,16,8};
__constant__ int cb_HW[4]  = {4096,1024,256,64};
__constant__ int cb_LW[4]  = {6,5,4,3};
__constant__ int cb_CUM[4] = {0,4096,5120,5376};
__constant__ int cb_lvl[43] = {0,0,0,0,0,0,0,0,0,0,0,0,0,0,0,0,
                               0,0,0,0,0,0,0,0,0,0,0,0,0,0,0,0,
                               1,1,1,1,1,1,1,1, 2,2, 3};
__constant__ int cb_pix[43] = {0,128,256,384,512,640,768,896,1024,1152,1280,1408,
                               1536,1664,1792,1920,2048,2176,2304,2432,2560,2688,
                               2816,2944,3072,3200,3328,3456,3584,3712,3840,3968,
                               0,128,256,384,512,640,768,896, 0,128, 0};

__device__ __constant__ float c_sizes[4][3] = {
    {32.f,40.f,50.f},{64.f,80.f,101.f},{128.f,161.f,203.f},{256.f,322.f,406.f}};
__device__ __constant__ float c_ratios[3] = {0.5f,1.0f,2.0f};
__device__ __constant__ int   c_str[4] = {8,16,32,64};

#define OFF_CLS_TW 0
#define OFF_REG_TW 2359296
#define OFF_CLS_OW 4718592
#define OFF_REG_OW 6488064
#define WT_TOTAL   6782976

__device__ __align__(16) __half g_xh0[(size_t)8*5440*256];
__device__ __align__(16) __half g_xl0[(size_t)8*5440*256];
__device__ __align__(16) __half g_xh1[(size_t)8*5440*256];
__device__ __align__(16) __half g_xl1[(size_t)8*5440*256];
__device__ __align__(16) __half g_wth[WT_TOTAL];
__device__ __align__(16) __half g_wtl[WT_TOTAL];
__device__ __align__(16) float g_cls[BATCH*CLS_C*5440];
__device__ __align__(16) float g_reg[BATCH*REG_C*5440];
__device__ unsigned g_hist[16*65536];
__device__ unsigned g_thr[16];
__device__ int      g_cnt[16];
__device__ unsigned long long g_cand[(size_t)16*CAPB];
__device__ unsigned long long g_sel[16*DPI];
__device__ float g_cbox[BATCH*400*4];
__device__ float g_cscore[BATCH*400];
__device__ int   g_clab[BATCH*400];

__device__ __forceinline__ unsigned fkey(float f){
    unsigned b=__float_as_uint(f);
    return b ^ ((b>>31) ? 0xFFFFFFFFu : 0x80000000u);
}
__device__ __forceinline__ float unfkey(unsigned u){
    unsigned b=u ^ ((u>>31) ? 0x80000000u : 0xFFFFFFFFu);
    return __uint_as_float(b);
}
__device__ __forceinline__ void mma_f16(float* c, const uint4& a,
                                        unsigned b0, unsigned b1){
    asm("mma.sync.aligned.m16n8k16.row.col.f32.f16.f16.f32 "
        "{%0,%1,%2,%3},{%4,%5,%6,%7},{%8,%9},{%0,%1,%2,%3};"
        : "+f"(c[0]),"+f"(c[1]),"+f"(c[2]),"+f"(c[3])
        : "r"(a.x),"r"(a.y),"r"(a.z),"r"(a.w),"r"(b0),"r"(b1));
}
__device__ __forceinline__ unsigned smem_u32(const void* p){
    unsigned a;
    asm("{ .reg .u64 t; cvta.to.shared.u64 t, %1; cvt.u32.u64 %0, t; }"
        : "=r"(a) : "l"(p));
    return a;
}
__device__ __forceinline__ void cp16(unsigned dst, const void* src, int sz){
    asm volatile("cp.async.cg.shared.global [%0], [%1], 16, %2;"
                 :: "r"(dst), "l"(src), "r"(sz));
}
#define CP_COMMIT() asm volatile("cp.async.commit_group;" ::: "memory")
#define CP_WAIT0()  asm volatile("cp.async.wait_group 0;" ::: "memory")
#define CP_WAIT1()  asm volatile("cp.async.wait_group 1;" ::: "memory")
#define CP_WAIT2()  asm volatile("cp.async.wait_group 2;" ::: "memory")

__global__ void prep_k(const float* __restrict__ f0,const float* __restrict__ f1,
                       const float* __restrict__ f2,const float* __restrict__ f3,
                       __half* __restrict__ oh,__half* __restrict__ ol){
    size_t total=(size_t)4*5440*256;
    for(size_t e=(size_t)blockIdx.x*blockDim.x+threadIdx.x;e<total;
        e+=(size_t)gridDim.x*blockDim.x){
        int ci=(int)(e&255);
        int pixG=(int)((e>>8)%5440);
        int b=(int)(e/(5440*256));
        int lvl = pixG<4096?0 : pixG<5120?1 : pixG<5376?2 : 3;
        int cum = lvl==0?0 : lvl==1?4096 : lvl==2?5120 : 5376;
        int HW  = lvl==0?4096 : lvl==1?1024 : lvl==2?256 : 64;
        const float* f = lvl==0?f0 : lvl==1?f1 : lvl==2?f2 : f3;
        float v = f[((size_t)b*256+ci)*HW + (pixG-cum)];
        __half h=__float2half(v);
        oh[e]=h; ol[e]=__float2half(v-__half2float(h));
    }
}

// weight transform+split into m16n8k16 fragment-major packed fp16 hi/lo
__global__ void wtrans_k(const float* __restrict__ src,
                         __half* __restrict__ dh, __half* __restrict__ dl,
                         int Cout,int nTiles,int nL){
    size_t total=(size_t)nL*9*nTiles*32768;
    for(size_t e=(size_t)blockIdx.x*blockDim.x+threadIdx.x;e<total;
        e+=(size_t)gridDim.x*blockDim.x){
        int h2=(int)(e&1);
        size_t s=e>>1;
        int v=(int)(s&3);
        int lane=(int)((s>>2)&31);
        int fm=(int)((s>>7)&3);
        int wm=(int)((s>>9)&1);
        int ki=(int)((s>>10)&1);
        int cchunk=(int)((s>>11)&7);
        size_t t=s>>14;
        int ct=(int)(t%nTiles); t/=nTiles;
        int kpos=(int)(t%9); int layer=(int)(t/9);
        int lr=lane>>2, lc=lane&3;
        int co=ct*128 + wm*64 + fm*16 + (v&1)*8 + lr;
        int k =cchunk*32 + ki*16 + (v>>1)*8 + 2*lc + h2;
        float val=0.f;
        if(co<Cout) val=src[(((size_t)layer*Cout+co)*256+k)*9+kpos];
        __half hi=__float2half(val);
        dh[e]=hi; dl[e]=__float2half(val-__half2float(hi));
    }
}

// 3xFP16 m16n8k16 conv core, 4-stage cp.async.
// stage: Ahi 8192B | Alo 8192B | Bhi 10240B (128 rows x 40 halves) | Blo 10240B
#define STAGEB 36864
#define SMEMBYTES (4*STAGEB)

__device__ void conv_mma(
    const __half* __restrict__ Xh, const __half* __restrict__ Xl,
    const __half* __restrict__ Whh, const __half* __restrict__ Whl,
    int nTiles, int ct, const float* __restrict__ bias,
    int W, int HW, int lw, int pixBase,
    int mode, int Cout, int relu,
    __half* __restrict__ outH, __half* __restrict__ outL,
    float* __restrict__ outF,
    int cum, char* smem)
{
    Xh += (size_t)cum*256;
    Xl += (size_t)cum*256;

    const int tid=threadIdx.x;
    const int lane=tid&31, wid=tid>>5;
    const int wm=wid&1, wn=wid>>1;
    const int lr=lane>>2, lc=lane&3;
    const int coBase=ct*128;

    int validPx = HW - pixBase; if(validPx>128) validPx=128;

    const int srow=tid>>1, half=tid&1;
    const int q=pixBase+srow;
    const bool rowv = srow<validPx;
    const int hh=q>>lw, ww=q&(W-1);

    const unsigned sb = smem_u32(smem);

    float acc[4][4][4];
#pragma unroll
    for(int i=0;i<4;i++)
#pragma unroll
        for(int j=0;j<4;j++)
#pragma unroll
            for(int r=0;r<4;r++) acc[i][j][r]=0.f;

    auto stage=[&](int ch,int s){
        const int kpos=ch>>3, cc=ch&7;
        const unsigned base = sb + (unsigned)(s*STAGEB);
        const __half* awh=Whh + ((size_t)(kpos*nTiles+ct))*32768 + cc*4096 + tid*16;
        const __half* awl=Whl + ((size_t)(kpos*nTiles+ct))*32768 + cc*4096 + tid*16;
        cp16(base + tid*32,          awh,   16);
        cp16(base + tid*32+16,       awh+8, 16);
        cp16(base + 8192 + tid*32,   awl,   16);
        cp16(base + 8192 + tid*32+16,awl+8, 16);
        const int dh=kpos/3-1, dw=kpos-(kpos/3)*3-1;
        const int hs=hh+dh, ws=ww+dw;
        const bool ok = rowv && (unsigned)hs<(unsigned)W && (unsigned)ws<(unsigned)W;
        const size_t xoff = ok ? ((size_t)(hs*W+ws)*256) : 0;
        const int sz = ok?16:0;
        const __half* xh = Xh + xoff + cc*32 + half*16;
        const __half* xl = Xl + xoff + cc*32 + half*16;
        const unsigned bh = base + 16384 + (unsigned)((srow*40 + half*16)*2);
        const unsigned bl = base + 26624 + (unsigned)((srow*40 + half*16)*2);
        cp16(bh,    xh,   sz);
        cp16(bh+16, xh+8, sz);
        cp16(bl,    xl,   sz);
        cp16(bl+16, xl+8, sz);
    };

    stage(0,0); CP_COMMIT();
    stage(1,1); CP_COMMIT();
    stage(2,2); CP_COMMIT();

    for(int ch=0;ch<72;ch++){
        const int s=ch&3;
        if(ch<70) CP_WAIT2();
        else if(ch==70) CP_WAIT1();
        else CP_WAIT0();
        __syncthreads();
        if(ch+3<72){ stage(ch+3,(ch+3)&3); CP_COMMIT(); }
        char* S = smem + s*STAGEB;
#pragma unroll
        for(int ki=0;ki<2;ki++){
            uint4 AH[4], AL[4];
#pragma unroll
            for(int fm=0;fm<4;fm++){
                const int fo=((((ki*2+wm)*4+fm)*32+lane))*16;
                AH[fm]=*(const uint4*)(S + fo);
                AL[fm]=*(const uint4*)(S + 8192 + fo);
            }
#pragma unroll
            for(int fn=0;fn<4;fn++){
                const int nr=(wn<<5)+(fn<<3)+lr;
                const int bo=(nr*40 + ki*16 + 2*lc)*2;
                unsigned bh0=*(const unsigned*)(S + 16384 + bo);
                unsigned bh1=*(const unsigned*)(S + 16384 + bo + 16);
                unsigned bl0=*(const unsigned*)(S + 26624 + bo);
                unsigned bl1=*(const unsigned*)(S + 26624 + bo + 16);
#pragma unroll
                for(int fm=0;fm<4;fm++){
                    mma_f16(acc[fm][fn], AH[fm], bh0, bh1);
                    mma_f16(acc[fm][fn], AH[fm], bl0, bl1);
                    mma_f16(acc[fm][fn], AL[fm], bh0, bh1);
                }
            }
        }
    }

#pragma unroll
    for(int fm=0;fm<4;fm++){
#pragma unroll
        for(int fn=0;fn<4;fn++){
            int m0=(wm<<6)+(fm<<4)+lr;
            int n0=(wn<<5)+(fn<<3)+(lc<<1);
            const float* a=acc[fm][fn];
#pragma unroll
            for(int r=0;r<4;r++){
                int m=m0+((r>>1)<<3);
                int n=n0+(r&1);
                if(n>=validPx) continue;
                int co=coBase+m;
                if(mode==0){
                    float v=a[r]+bias[co];
                    if(relu) v=fmaxf(v,0.f);
                    __half hv=__float2half(v);
                    size_t ad=((size_t)(cum+pixBase+n))*256+co;
                    outH[ad]=hv;
                    outL[ad]=__float2half(v-__half2float(hv));
                }else{
                    if(co<Cout)
                        outF[(size_t)co*HW + pixBase + n]=a[r]+bias[co];
                }
            }
        }
    }
}

__global__ __launch_bounds__(256,1)
void conv_tower_k(const __half* __restrict__ Xh,const __half* __restrict__ Xl,
                  const __half* __restrict__ wCh,const __half* __restrict__ wCl,
                  const __half* __restrict__ wRh,const __half* __restrict__ wRl,
                  const float* __restrict__ bC,const float* __restrict__ bR,
                  __half* __restrict__ XhO,__half* __restrict__ XlO,int first){
    extern __shared__ char smem[];
    const int bx=blockIdx.x;
    const int lvl=cb_lvl[bx], pixBase=cb_pix[bx];
    const int tower=blockIdx.y>>1, ct=blockIdx.y&1;
    const int b=blockIdx.z;
    const int W=cb_W[lvl],HW=cb_HW[lvl],lw=cb_LW[lvl],cum=cb_CUM[lvl];
    int inSlot = first ? b : (tower*4+b);
    int outSlot = tower*4+b;
    conv_mma(Xh+(size_t)inSlot*5440*256, Xl+(size_t)inSlot*5440*256,
             tower?wRh:wCh, tower?wRl:wCl, 2, ct, tower?bR:bC,
             W,HW,lw,pixBase, 0,256,1,
             XhO+(size_t)outSlot*5440*256, XlO+(size_t)outSlot*5440*256,
             0, cum, smem);
}

__global__ __launch_bounds__(256,1)
void conv_head_k(const __half* __restrict__ Xh,const __half* __restrict__ Xl,
                 const __half* __restrict__ wCh,const __half* __restrict__ wCl,
                 const __half* __restrict__ wRh,const __half* __restrict__ wRl,
                 const float* __restrict__ cob,const float* __restrict__ rob,
                 float* __restrict__ cls,float* __restrict__ reg){
    extern __shared__ char smem[];
    const int bx=blockIdx.x;
    const int lvl=cb_lvl[bx], pixBase=cb_pix[bx];
    const int y=blockIdx.y, b=blockIdx.z;
    const int W=cb_W[lvl],HW=cb_HW[lvl],lw=cb_LW[lvl],cum=cb_CUM[lvl];
    if(y<6){
        conv_mma(Xh+(size_t)b*5440*256, Xl+(size_t)b*5440*256,
                 wCh, wCl, 6, y, cob,
                 W,HW,lw,pixBase, 1,720,0, 0,0,
                 cls + (size_t)CLS_C*4*cum + (size_t)b*CLS_C*HW, cum, smem);
    }else{
        conv_mma(Xh+(size_t)(4+b)*5440*256, Xl+(size_t)(4+b)*5440*256,
                 wRh, wRl, 1, 0, rob,
                 W,HW,lw,pixBase, 1,36,0, 0,0,
                 reg + (size_t)REG_C*4*cum + (size_t)b*REG_C*HW, cum, smem);
    }
}

__device__ __forceinline__ float sigm(float v){ return 1.0f/(1.0f+expf(-v)); }
__device__ __forceinline__ bool is_cand(float v){
    if(v>-2.93f) return true;
    if(v<=-2.96f) return false;
    return sigm(v)>0.05f;
}

__global__ void zero_k(){
    int i=blockIdx.x*blockDim.x+threadIdx.x;
    if(i<16*65536) g_hist[i]=0;
    if(i<16) g_cnt[i]=0;
}

__global__ void hist_k(const float* __restrict__ cls){
    const int g=blockIdx.y, b=g>>2, lvl=g&3;
    const int HW=cb_HW[lvl], n=CLS_C*HW;
    const float* p=cls + (size_t)CLS_C*4*cb_CUM[lvl] + (size_t)b*n;
    for(int m=blockIdx.x*blockDim.x+threadIdx.x;m<n;m+=gridDim.x*blockDim.x){
        float v=p[m];
        if(is_cand(v)) atomicAdd(&g_hist[g*65536+(fkey(sigm(v))>>16)],1u);
    }
}

__global__ void scan_k(){
    const int g=blockIdx.x;
    __shared__ unsigned seg[256];
    const unsigned* h=&g_hist[g*65536];
    unsigned s=0; int base=threadIdx.x*256;
    for(int k=0;k<256;k++) s+=h[65535-(base+k)];
    seg[threadIdx.x]=s;
    __syncthreads();
    if(threadIdx.x==0){
        unsigned cum=0,thr=0;
        for(int sg=0;sg<256;sg++){
            if(cum+seg[sg]>=DPI){
                for(int k=0;k<256;k++){
                    cum+=h[65535-(sg*256+k)];
                    if(cum>=DPI){thr=65535-(sg*256+k);break;}
                }
                break;
            }
            cum+=seg[sg];
        }
        g_thr[g]=thr;
    }
}

__global__ void collect_k(const float* __restrict__ cls){
    const int g=blockIdx.y, b=g>>2, lvl=g&3;
    const int HW=cb_HW[lvl], n=CLS_C*HW;
    const unsigned thr=g_thr[g];
    const float* p=cls + (size_t)CLS_C*4*cb_CUM[lvl] + (size_t)b*n;
    for(int m=blockIdx.x*blockDim.x+threadIdx.x;m<n;m+=gridDim.x*blockDim.x){
        float v=p[m];
        if(!is_cand(v)) continue;
        unsigned u=fkey(sigm(v));
        if((u>>16)>=thr){
            int pos=atomicAdd(&g_cnt[g],1);
            if(pos<CAPB){
                int co=m/HW, pix=m-co*HW;
                unsigned nn=(unsigned)(pix*CLS_C+co);
                g_cand[(size_t)g*CAPB+pos]=((unsigned long long)u<<32)|(0xFFFFFFFFu-nn);
            }
        }
    }
}

__global__ __launch_bounds__(256)
void select_k(){
    const int g=blockIdx.x;
    int cnt=g_cnt[g]; if(cnt>CAPB) cnt=CAPB;
    unsigned long long* cand=&g_cand[(size_t)g*CAPB];
    __shared__ unsigned long long sc[4096];
    __shared__ unsigned long long wmax[8];
    __shared__ int wpos[8];
    const int tid=threadIdx.x, lane=tid&31, wid=tid>>5;
    const bool cached = cnt<=4096;
    if(cached) for(int i=tid;i<cnt;i+=256) sc[i]=cand[i];
    __syncthreads();
    unsigned long long* src = cached? sc : cand;
    for(int r=0;r<DPI;r++){
        unsigned long long mk=0ULL; int mp=-1;
        for(int i=tid;i<cnt;i+=256){
            unsigned long long k=src[i];
            if(k>mk){mk=k;mp=i;}
        }
#pragma unroll
        for(int off=16;off>0;off>>=1){
            unsigned long long ok=__shfl_down_sync(0xFFFFFFFFu,mk,off);
            int op=__shfl_down_sync(0xFFFFFFFFu,mp,off);
            if(ok>mk){mk=ok;mp=op;}
        }
        if(lane==0){wmax[wid]=mk;wpos[wid]=mp;}
        __syncthreads();
        if(tid==0){
            unsigned long long bk=wmax[0]; int bp=wpos[0];
#pragma unroll
            for(int w=1;w<8;w++) if(wmax[w]>bk){bk=wmax[w];bp=wpos[w];}
            g_sel[g*DPI+r]=bk;
            if(bp>=0) src[bp]=0ULL;
        }
        __syncthreads();
    }
}

__global__ void decode_k(const float* __restrict__ reg,
                         const int* __restrict__ ph,const int* __restrict__ pw){
    const int g=blockIdx.x, b=g>>2, lvl=g&3;
    const int r=threadIdx.x;
    if(r>=DPI) return;
    const int W=cb_W[lvl], HW=cb_HW[lvl];
    const float ih=(float)(*ph), iw=(float)(*pw);
    const int slot=b*400+lvl*DPI+r;
    unsigned long long k=g_sel[g*DPI+r];
    float* bx=&g_cbox[(size_t)slot*4];
    if(!k){ g_cscore[slot]=-1.f; g_clab[slot]=-1; bx[0]=bx[1]=bx[2]=bx[3]=0.f; return; }
    float sc=unfkey((unsigned)(k>>32));
    unsigned n=0xFFFFFFFFu-(unsigned)(k&0xFFFFFFFFu);
    int pix=(int)(n/CLS_C); int co=(int)(n-(unsigned)pix*CLS_C);
    int a=co/NC, c=co-a*NC;
    int hh=pix/W, ww=pix-hh*W;
    float size=c_sizes[lvl][a%3];
    float hr=sqrtf(c_ratios[a/3]);
    float wr=1.f/hr;
    float ws=wr*size, hs=hr*size;
    float st=(float)c_str[lvl];
    float sx=(float)ww*st, sy=(float)hh*st;
    float ax1=fminf(fmaxf(sx+rintf(-ws*0.5f),0.f),iw);
    float ay1=fminf(fmaxf(sy+rintf(-hs*0.5f),0.f),ih);
    float ax2=fminf(fmaxf(sx+rintf( ws*0.5f),0.f),iw);
    float ay2=fminf(fmaxf(sy+rintf( hs*0.5f),0.f),ih);
    float aw=ax2-ax1, ah=ay2-ay1;
    float cx=ax1+0.5f*aw, cy=ay1+0.5f*ah;
    const float* R=reg + (size_t)REG_C*4*cb_CUM[lvl] + (size_t)b*REG_C*HW;
    float dx=R[(a*4+0)*HW+pix];
    float dy=R[(a*4+1)*HW+pix];
    const float CLIPV=(float)4.135166556742356;
    float dw=fminf(R[(a*4+2)*HW+pix],CLIPV);
    float dh=fminf(R[(a*4+3)*HW+pix],CLIPV);
    float pcx=dx*aw+cx, pcy=dy*ah+cy;
    float pw_=expf(dw)*aw, ph_=expf(dh)*ah;
    bx[0]=fminf(fmaxf(pcx-0.5f*pw_,0.f),iw);
    bx[1]=fminf(fmaxf(pcy-0.5f*ph_,0.f),ih);
    bx[2]=fminf(fmaxf(pcx+0.5f*pw_,0.f),iw);
    bx[3]=fminf(fmaxf(pcy+0.5f*ph_,0.f),ih);
    g_cscore[slot]=sc;
    g_clab[slot]=c;
}

__global__ __launch_bounds__(512)
void final_k(float* __restrict__ out,const int* __restrict__ ph,const int* __restrict__ pw){
    int b=blockIdx.x, tid=threadIdx.x;
    __shared__ unsigned long long key[512];
    __shared__ float X1[512],Y1[512],X2[512],Y2[512],AR[512],SC[512];
    __shared__ float BX1[512],BY1[512],BX2[512],BY2[512];
    __shared__ int LB[512];
    __shared__ unsigned char KP[512];
    float ih=(float)(*ph), iw=(float)(*pw);
    float ob=fmaxf(ih,iw)+1.f;
    if(tid<400)
        key[tid]=((unsigned long long)fkey(g_cscore[b*400+tid])<<32)|(0xFFFFFFFFu-(unsigned)tid);
    else key[tid]=0ULL;
    __syncthreads();
    for(int k=2;k<=512;k<<=1)
        for(int j=k>>1;j>0;j>>=1){
            int ix=tid^j;
            if(ix>tid){
                unsigned long long a=key[tid],c=key[ix];
                if((a>c)==((tid&k)==0)){key[tid]=c;key[ix]=a;}
            }
            __syncthreads();
        }
    {
        unsigned long long k=key[511-tid];
        float sc=-1.f; int lb=-1; float b0=0,b1=0,b2=0,b3=0;
        if(k){
            unsigned i=0xFFFFFFFFu-(unsigned)(k&0xFFFFFFFFu);
            sc=unfkey((unsigned)(k>>32));
            lb=g_clab[b*400+i];
            const float* bp=&g_cbox[((size_t)b*400+i)*4];
            b0=bp[0];b1=bp[1];b2=bp[2];b3=bp[3];
        }
        float o=(float)lb*ob;
        BX1[tid]=b0;BY1[tid]=b1;BX2[tid]=b2;BY2[tid]=b3;
        X1[tid]=b0+o;Y1[tid]=b1+o;X2[tid]=b2+o;Y2[tid]=b3+o;
        SC[tid]=sc;LB[tid]=lb;
        AR[tid]=(X2[tid]-X1[tid])*(Y2[tid]-Y1[tid]);
        KP[tid]=(sc>0.05f)?1:0;
    }
    __syncthreads();
    for(int i=0;i<400;i++){
        if(KP[i]&&tid>i&&tid<400&&KP[tid]){
            float w=fmaxf(fminf(X2[i],X2[tid])-fmaxf(X1[i],X1[tid]),0.f);
            float h=fmaxf(fminf(Y2[i],Y2[tid])-fmaxf(Y1[i],Y1[tid]),0.f);
            float it=w*h;
            float iou=it/(AR[i]+AR[tid]-it+1e-9f);
            if(iou>0.5f) KP[tid]=0;
        }
        __syncthreads();
    }
    if(tid==0){
        int o=0;
        for(int r=0;r<400&&o<DPI;r++) if(KP[r]){
            out[(b*DPI+o)*4+0]=BX1[r]; out[(b*DPI+o)*4+1]=BY1[r];
            out[(b*DPI+o)*4+2]=BX2[r]; out[(b*DPI+o)*4+3]=BY2[r];
            out[1600+b*DPI+o]=SC[r];   out[2000+b*DPI+o]=(float)LB[r];
            o++;
        }
        for(;o<DPI;o++){
            out[(b*DPI+o)*4+0]=0.f; out[(b*DPI+o)*4+1]=0.f;
            out[(b*DPI+o)*4+2]=0.f; out[(b*DPI+o)*4+3]=0.f;
            out[1600+b*DPI+o]=0.f;  out[2000+b*DPI+o]=-1.f;
        }
    }
}

extern "C" void kernel_launch(void* const* d_in, const int* in_sizes, int n_in,
                              void* d_out, int out_size){
    const float* f0=(const float*)d_in[0];
    const float* f1=(const float*)d_in[1];
    const float* f2=(const float*)d_in[2];
    const float* f3=(const float*)d_in[3];
    const float* ctw=(const float*)d_in[4];
    const float* ctb=(const float*)d_in[5];
    const float* cow=(const float*)d_in[6];
    const float* cob=(const float*)d_in[7];
    const float* rtw=(const float*)d_in[8];
    const float* rtb=(const float*)d_in[9];
    const float* row_=(const float*)d_in[10];
    const float* rob=(const float*)d_in[11];
    const int* ph=(const int*)d_in[12];
    const int* pw=(const int*)d_in[13];

    __half *xh0,*xl0,*xh1,*xl1,*wh,*wl;
    float *cls,*reg;
    cudaGetSymbolAddress((void**)&xh0,g_xh0);
    cudaGetSymbolAddress((void**)&xl0,g_xl0);
    cudaGetSymbolAddress((void**)&xh1,g_xh1);
    cudaGetSymbolAddress((void**)&xl1,g_xl1);
    cudaGetSymbolAddress((void**)&cls,g_cls);
    cudaGetSymbolAddress((void**)&reg,g_reg);
    cudaGetSymbolAddress((void**)&wh,g_wth);
    cudaGetSymbolAddress((void**)&wl,g_wtl);

    cudaFuncSetAttribute(conv_tower_k, cudaFuncAttributeMaxDynamicSharedMemorySize, SMEMBYTES);
    cudaFuncSetAttribute(conv_head_k,  cudaFuncAttributeMaxDynamicSharedMemorySize, SMEMBYTES);

    prep_k<<<2048,256>>>(f0,f1,f2,f3,xh0,xl0);
    wtrans_k<<<2048,256>>>(ctw, wh+OFF_CLS_TW, wl+OFF_CLS_TW, 256,2,4);
    wtrans_k<<<2048,256>>>(rtw, wh+OFF_REG_TW, wl+OFF_REG_TW, 256,2,4);
    wtrans_k<<<2048,256>>>(cow, wh+OFF_CLS_OW, wl+OFF_CLS_OW, 720,6,1);
    wtrans_k<<<1024,256>>>(row_, wh+OFF_REG_OW, wl+OFF_REG_OW, 36,1,1);

    const size_t LSZ = 589824;
    conv_tower_k<<<dim3(43,4,BATCH),256,SMEMBYTES>>>(xh0,xl0,
        wh+OFF_CLS_TW+0*LSZ, wl+OFF_CLS_TW+0*LSZ,
        wh+OFF_REG_TW+0*LSZ, wl+OFF_REG_TW+0*LSZ, ctb+0,  rtb+0,  xh1,xl1, 1);
    conv_tower_k<<<dim3(43,4,BATCH),256,SMEMBYTES>>>(xh1,xl1,
        wh+OFF_CLS_TW+1*LSZ, wl+OFF_CLS_TW+1*LSZ,
        wh+OFF_REG_TW+1*LSZ, wl+OFF_REG_TW+1*LSZ, ctb+256,rtb+256,xh0,xl0, 0);
    conv_tower_k<<<dim3(43,4,BATCH),256,SMEMBYTES>>>(xh0,xl0,
        wh+OFF_CLS_TW+2*LSZ, wl+OFF_CLS_TW+2*LSZ,
        wh+OFF_REG_TW+2*LSZ, wl+OFF_REG_TW+2*LSZ, ctb+512,rtb+512,xh1,xl1, 0);
    conv_tower_k<<<dim3(43,4,BATCH),256,SMEMBYTES>>>(xh1,xl1,
        wh+OFF_CLS_TW+3*LSZ, wl+OFF_CLS_TW+3*LSZ,
        wh+OFF_REG_TW+3*LSZ, wl+OFF_REG_TW+3*LSZ, ctb+768,rtb+768,xh0,xl0, 0);
    conv_head_k<<<dim3(43,7,BATCH),256,SMEMBYTES>>>(xh0,xl0,
        wh+OFF_CLS_OW, wl+OFF_CLS_OW, wh+OFF_REG_OW, wl+OFF_REG_OW,
        cob, rob, cls, reg);

    zero_k<<<4096,256>>>();
    hist_k<<<dim3(256,16),256>>>(cls);
    scan_k<<<16,256>>>();
    collect_k<<<dim3(256,16),256>>>(cls);
    select_k<<<16,256>>>();
    decode_k<<<16,128>>>(reg,ph,pw);
    final_k<<<BATCH,512>>>((float*)d_out,ph,pw);
}

// round 16
// speedup vs baseline: 2.4027x; 1.1287x over previous
#include <cuda_runtime.h>
#include <cuda_fp16.h>
#include <math.h>

#define NC 80
#define CLS_C 720
#define REG_C 36
#define DPI 100
#define BATCH 4
#define CAPB 131072

__constant__ int cb_W[4]   = {64,32,16,8};
__constant__ int cb_HW[4]  = {4096,1024,256,64};
__constant__ int cb_LW[4]  = {6,5,4,3};
__constant__ int cb_CUM[4] = {0,4096,5120,5376};
__constant__ int cb_lvl[43] = {0,0,0,0,0,0,0,0,0,0,0,0,0,0,0,0,
                               0,0,0,0,0,0,0,0,0,0,0,0,0,0,0,0,
                               1,1,1,1,1,1,1,1, 2,2, 3};
__constant__ int cb_pix[43] = {0,128,256,384,512,640,768,896,1024,1152,1280,1408,
                               1536,1664,1792,1920,2048,2176,2304,2432,2560,2688,
                               2816,2944,3072,3200,3328,3456,3584,3712,3840,3968,
                               0,128,256,384,512,640,768,896, 0,128, 0};

__device__ __constant__ float c_sizes[4][3] = {
    {32.f,40.f,50.f},{64.f,80.f,101.f},{128.f,161.f,203.f},{256.f,322.f,406.f}};
__device__ __constant__ float c_ratios[3] = {0.5f,1.0f,2.0f};
__device__ __constant__ int   c_str[4] = {8,16,32,64};

#define OFF_CLS_TW 0
#define OFF_REG_TW 2359296
#define OFF_CLS_OW 4718592
#define OFF_REG_OW 6488064
#define WT_TOTAL   6782976

__device__ __align__(16) __half g_xh0[(size_t)8*5440*256];
__device__ __align__(16) __half g_xl0[(size_t)8*5440*256];
__device__ __align__(16) __half g_xh1[(size_t)8*5440*256];
__device__ __align__(16) __half g_xl1[(size_t)8*5440*256];
__device__ __align__(16) __half g_wth[WT_TOTAL];
__device__ __align__(16) __half g_wtl[WT_TOTAL];
__device__ __align__(16) float g_cls[BATCH*CLS_C*5440];
__device__ __align__(16) float g_reg[BATCH*REG_C*5440];
__device__ unsigned g_hist[16*65536];
__device__ unsigned g_thr[16];
__device__ int      g_cnt[16];
__device__ unsigned long long g_cand[(size_t)16*CAPB];
__device__ unsigned long long g_sel[16*DPI];
__device__ float g_cbox[BATCH*400*4];
__device__ float g_cscore[BATCH*400];
__device__ int   g_clab[BATCH*400];

__device__ __forceinline__ unsigned fkey(float f){
    unsigned b=__float_as_uint(f);
    return b ^ ((b>>31) ? 0xFFFFFFFFu : 0x80000000u);
}
__device__ __forceinline__ float unfkey(unsigned u){
    unsigned b=u ^ ((u>>31) ? 0x80000000u : 0xFFFFFFFFu);
    return __uint_as_float(b);
}
__device__ __forceinline__ void mma_f16(float* c, const uint4& a,
                                        unsigned b0, unsigned b1){
    asm("mma.sync.aligned.m16n8k16.row.col.f32.f16.f16.f32 "
        "{%0,%1,%2,%3},{%4,%5,%6,%7},{%8,%9},{%0,%1,%2,%3};"
        : "+f"(c[0]),"+f"(c[1]),"+f"(c[2]),"+f"(c[3])
        : "r"(a.x),"r"(a.y),"r"(a.z),"r"(a.w),"r"(b0),"r"(b1));
}
__device__ __forceinline__ unsigned smem_u32(const void* p){
    unsigned a;
    asm("{ .reg .u64 t; cvta.to.shared.u64 t, %1; cvt.u32.u64 %0, t; }"
        : "=r"(a) : "l"(p));
    return a;
}
__device__ __forceinline__ void cp16(unsigned dst, const void* src, int sz){
    asm volatile("cp.async.cg.shared.global [%0], [%1], 16, %2;"
                 :: "r"(dst), "l"(src), "r"(sz));
}
#define CP_COMMIT() asm volatile("cp.async.commit_group;" ::: "memory")
#define CP_WAIT0()  asm volatile("cp.async.wait_group 0;" ::: "memory")
#define CP_WAIT1()  asm volatile("cp.async.wait_group 1;" ::: "memory")

__global__ void prep_k(const float* __restrict__ f0,const float* __restrict__ f1,
                       const float* __restrict__ f2,const float* __restrict__ f3,
                       __half* __restrict__ oh,__half* __restrict__ ol){
    size_t total=(size_t)4*5440*256;
    for(size_t e=(size_t)blockIdx.x*blockDim.x+threadIdx.x;e<total;
        e+=(size_t)gridDim.x*blockDim.x){
        int ci=(int)(e&255);
        int pixG=(int)((e>>8)%5440);
        int b=(int)(e/(5440*256));
        int lvl = pixG<4096?0 : pixG<5120?1 : pixG<5376?2 : 3;
        int cum = lvl==0?0 : lvl==1?4096 : lvl==2?5120 : 5376;
        int HW  = lvl==0?4096 : lvl==1?1024 : lvl==2?256 : 64;
        const float* f = lvl==0?f0 : lvl==1?f1 : lvl==2?f2 : f3;
        float v = f[((size_t)b*256+ci)*HW + (pixG-cum)];
        __half h=__float2half(v);
        oh[e]=h; ol[e]=__float2half(v-__half2float(h));
    }
}

__global__ void wtrans_k(const float* __restrict__ src,
                         __half* __restrict__ dh, __half* __restrict__ dl,
                         int Cout,int nTiles,int nL){
    size_t total=(size_t)nL*9*nTiles*32768;
    for(size_t e=(size_t)blockIdx.x*blockDim.x+threadIdx.x;e<total;
        e+=(size_t)gridDim.x*blockDim.x){
        int h2=(int)(e&1);
        size_t s=e>>1;
        int v=(int)(s&3);
        int lane=(int)((s>>2)&31);
        int fm=(int)((s>>7)&3);
        int wm=(int)((s>>9)&1);
        int ki=(int)((s>>10)&1);
        int cchunk=(int)((s>>11)&7);
        size_t t=s>>14;
        int ct=(int)(t%nTiles); t/=nTiles;
        int kpos=(int)(t%9); int layer=(int)(t/9);
        int lr=lane>>2, lc=lane&3;
        int co=ct*128 + wm*64 + fm*16 + (v&1)*8 + lr;
        int k =cchunk*32 + ki*16 + (v>>1)*8 + 2*lc + h2;
        float val=0.f;
        if(co<Cout) val=src[(((size_t)layer*Cout+co)*256+k)*9+kpos];
        __half hi=__float2half(val);
        dh[e]=hi; dl[e]=__float2half(val-__half2float(hi));
    }
}

// 3xFP16 m16n8k16 conv core, 3-stage cp.async ring, 2 blocks/SM.
#define STAGEB 36864
#define SMEMBYTES (3*STAGEB)

__device__ void conv_mma(
    const __half* __restrict__ Xh, const __half* __restrict__ Xl,
    const __half* __restrict__ Whh, const __half* __restrict__ Whl,
    int nTiles, int ct, const float* __restrict__ bias,
    int W, int HW, int lw, int pixBase,
    int mode, int Cout, int relu,
    __half* __restrict__ outH, __half* __restrict__ outL,
    float* __restrict__ outF,
    int cum, char* smem)
{
    Xh += (size_t)cum*256;
    Xl += (size_t)cum*256;

    const int tid=threadIdx.x;
    const int lane=tid&31, wid=tid>>5;
    const int wm=wid&1, wn=wid>>1;
    const int lr=lane>>2, lc=lane&3;
    const int coBase=ct*128;

    int validPx = HW - pixBase; if(validPx>128) validPx=128;

    const int srow=tid>>1, half=tid&1;
    const int q=pixBase+srow;
    const bool rowv = srow<validPx;
    const int hh=q>>lw, ww=q&(W-1);

    const unsigned sb = smem_u32(smem);

    float acc[4][4][4];
#pragma unroll
    for(int i=0;i<4;i++)
#pragma unroll
        for(int j=0;j<4;j++)
#pragma unroll
            for(int r=0;r<4;r++) acc[i][j][r]=0.f;

    auto stage=[&](int ch,int s){
        const int kpos=ch>>3, cc=ch&7;
        const unsigned base = sb + (unsigned)(s*STAGEB);
        const __half* awh=Whh + ((size_t)(kpos*nTiles+ct))*32768 + cc*4096 + tid*16;
        const __half* awl=Whl + ((size_t)(kpos*nTiles+ct))*32768 + cc*4096 + tid*16;
        cp16(base + tid*32,          awh,   16);
        cp16(base + tid*32+16,       awh+8, 16);
        cp16(base + 8192 + tid*32,   awl,   16);
        cp16(base + 8192 + tid*32+16,awl+8, 16);
        const int dh=kpos/3-1, dw=kpos-(kpos/3)*3-1;
        const int hs=hh+dh, ws=ww+dw;
        const bool ok = rowv && (unsigned)hs<(unsigned)W && (unsigned)ws<(unsigned)W;
        const size_t xoff = ok ? ((size_t)(hs*W+ws)*256) : 0;
        const int sz = ok?16:0;
        const __half* xh = Xh + xoff + cc*32 + half*16;
        const __half* xl = Xl + xoff + cc*32 + half*16;
        const unsigned bh = base + 16384 + (unsigned)((srow*40 + half*16)*2);
        const unsigned bl = base + 26624 + (unsigned)((srow*40 + half*16)*2);
        cp16(bh,    xh,   sz);
        cp16(bh+16, xh+8, sz);
        cp16(bl,    xl,   sz);
        cp16(bl+16, xl+8, sz);
    };

    stage(0,0); CP_COMMIT();
    stage(1,1); CP_COMMIT();

    int sbuf=0;
    for(int ch=0;ch<72;ch++){
        if(ch<71) CP_WAIT1(); else CP_WAIT0();
        __syncthreads();
        if(ch+2<72){
            int nb=sbuf+2; if(nb>=3) nb-=3;
            stage(ch+2, nb); CP_COMMIT();
        }
        char* S = smem + sbuf*STAGEB;
        sbuf++; if(sbuf>=3) sbuf=0;
#pragma unroll
        for(int ki=0;ki<2;ki++){
            uint4 AH[4], AL[4];
#pragma unroll
            for(int fm=0;fm<4;fm++){
                const int fo=((((ki*2+wm)*4+fm)*32+lane))*16;
                AH[fm]=*(const uint4*)(S + fo);
                AL[fm]=*(const uint4*)(S + 8192 + fo);
            }
#pragma unroll
            for(int fn=0;fn<4;fn++){
                const int nr=(wn<<5)+(fn<<3)+lr;
                const int bo=(nr*40 + ki*16 + 2*lc)*2;
                unsigned bh0=*(const unsigned*)(S + 16384 + bo);
                unsigned bh1=*(const unsigned*)(S + 16384 + bo + 16);
                unsigned bl0=*(const unsigned*)(S + 26624 + bo);
                unsigned bl1=*(const unsigned*)(S + 26624 + bo + 16);
#pragma unroll
                for(int fm=0;fm<4;fm++){
                    mma_f16(acc[fm][fn], AH[fm], bh0, bh1);
                    mma_f16(acc[fm][fn], AH[fm], bl0, bl1);
                    mma_f16(acc[fm][fn], AL[fm], bh0, bh1);
                }
            }
        }
    }

#pragma unroll
    for(int fm=0;fm<4;fm++){
#pragma unroll
        for(int fn=0;fn<4;fn++){
            int m0=(wm<<6)+(fm<<4)+lr;
            int n0=(wn<<5)+(fn<<3)+(lc<<1);
            const float* a=acc[fm][fn];
#pragma unroll
            for(int r=0;r<4;r++){
                int m=m0+((r>>1)<<3);
                int n=n0+(r&1);
                if(n>=validPx) continue;
                int co=coBase+m;
                if(mode==0){
                    float v=a[r]+bias[co];
                    if(relu) v=fmaxf(v,0.f);
                    __half hv=__float2half(v);
                    size_t ad=((size_t)(cum+pixBase+n))*256+co;
                    outH[ad]=hv;
                    outL[ad]=__float2half(v-__half2float(hv));
                }else{
                    if(co<Cout)
                        outF[(size_t)co*HW + pixBase + n]=a[r]+bias[co];
                }
            }
        }
    }
}

__global__ __launch_bounds__(256,2)
void conv_tower_k(const __half* __restrict__ Xh,const __half* __restrict__ Xl,
                  const __half* __restrict__ wCh,const __half* __restrict__ wCl,
                  const __half* __restrict__ wRh,const __half* __restrict__ wRl,
                  const float* __restrict__ bC,const float* __restrict__ bR,
                  __half* __restrict__ XhO,__half* __restrict__ XlO,int first){
    extern __shared__ char smem[];
    const int bx=blockIdx.x;
    const int lvl=cb_lvl[bx], pixBase=cb_pix[bx];
    const int tower=blockIdx.y>>1, ct=blockIdx.y&1;
    const int b=blockIdx.z;
    const int W=cb_W[lvl],HW=cb_HW[lvl],lw=cb_LW[lvl],cum=cb_CUM[lvl];
    int inSlot = first ? b : (tower*4+b);
    int outSlot = tower*4+b;
    conv_mma(Xh+(size_t)inSlot*5440*256, Xl+(size_t)inSlot*5440*256,
             tower?wRh:wCh, tower?wRl:wCl, 2, ct, tower?bR:bC,
             W,HW,lw,pixBase, 0,256,1,
             XhO+(size_t)outSlot*5440*256, XlO+(size_t)outSlot*5440*256,
             0, cum, smem);
}

__global__ __launch_bounds__(256,2)
void conv_head_k(const __half* __restrict__ Xh,const __half* __restrict__ Xl,
                 const __half* __restrict__ wCh,const __half* __restrict__ wCl,
                 const __half* __restrict__ wRh,const __half* __restrict__ wRl,
                 const float* __restrict__ cob,const float* __restrict__ rob,
                 float* __restrict__ cls,float* __restrict__ reg){
    extern __shared__ char smem[];
    const int bx=blockIdx.x;
    const int lvl=cb_lvl[bx], pixBase=cb_pix[bx];
    const int y=blockIdx.y, b=blockIdx.z;
    const int W=cb_W[lvl],HW=cb_HW[lvl],lw=cb_LW[lvl],cum=cb_CUM[lvl];
    if(y<6){
        conv_mma(Xh+(size_t)b*5440*256, Xl+(size_t)b*5440*256,
                 wCh, wCl, 6, y, cob,
                 W,HW,lw,pixBase, 1,720,0, 0,0,
                 cls + (size_t)CLS_C*4*cum + (size_t)b*CLS_C*HW, cum, smem);
    }else{
        conv_mma(Xh+(size_t)(4+b)*5440*256, Xl+(size_t)(4+b)*5440*256,
                 wRh, wRl, 1, 0, rob,
                 W,HW,lw,pixBase, 1,36,0, 0,0,
                 reg + (size_t)REG_C*4*cum + (size_t)b*REG_C*HW, cum, smem);
    }
}

__device__ __forceinline__ float sigm(float v){ return 1.0f/(1.0f+expf(-v)); }
__device__ __forceinline__ bool is_cand(float v){
    if(v>-2.93f) return true;
    if(v<=-2.96f) return false;
    return sigm(v)>0.05f;
}

__global__ void zero_k(){
    int i=blockIdx.x*blockDim.x+threadIdx.x;
    if(i<16*65536) g_hist[i]=0;
    if(i<16) g_cnt[i]=0;
}

__global__ void hist_k(const float* __restrict__ cls){
    const int g=blockIdx.y, b=g>>2, lvl=g&3;
    const int HW=cb_HW[lvl], n=CLS_C*HW;
    const float* p=cls + (size_t)CLS_C*4*cb_CUM[lvl] + (size_t)b*n;
    for(int m=blockIdx.x*blockDim.x+threadIdx.x;m<n;m+=gridDim.x*blockDim.x){
        float v=p[m];
        if(is_cand(v)) atomicAdd(&g_hist[g*65536+(fkey(sigm(v))>>16)],1u);
    }
}

__global__ void scan_k(){
    const int g=blockIdx.x;
    __shared__ unsigned seg[256];
    const unsigned* h=&g_hist[g*65536];
    unsigned s=0; int base=threadIdx.x*256;
    for(int k=0;k<256;k++) s+=h[65535-(base+k)];
    seg[threadIdx.x]=s;
    __syncthreads();
    if(threadIdx.x==0){
        unsigned cum=0,thr=0;
        for(int sg=0;sg<256;sg++){
            if(cum+seg[sg]>=DPI){
                for(int k=0;k<256;k++){
                    cum+=h[65535-(sg*256+k)];
                    if(cum>=DPI){thr=65535-(sg*256+k);break;}
                }
                break;
            }
            cum+=seg[sg];
        }
        g_thr[g]=thr;
    }
}

__global__ void collect_k(const float* __restrict__ cls){
    const int g=blockIdx.y, b=g>>2, lvl=g&3;
    const int HW=cb_HW[lvl], n=CLS_C*HW;
    const unsigned thr=g_thr[g];
    const float* p=cls + (size_t)CLS_C*4*cb_CUM[lvl] + (size_t)b*n;
    for(int m=blockIdx.x*blockDim.x+threadIdx.x;m<n;m+=gridDim.x*blockDim.x){
        float v=p[m];
        if(!is_cand(v)) continue;
        unsigned u=fkey(sigm(v));
        if((u>>16)>=thr){
            int pos=atomicAdd(&g_cnt[g],1);
            if(pos<CAPB){
                int co=m/HW, pix=m-co*HW;
                unsigned nn=(unsigned)(pix*CLS_C+co);
                g_cand[(size_t)g*CAPB+pos]=((unsigned long long)u<<32)|(0xFFFFFFFFu-nn);
            }
        }
    }
}

__global__ __launch_bounds__(256)
void select_k(){
    const int g=blockIdx.x;
    int cnt=g_cnt[g]; if(cnt>CAPB) cnt=CAPB;
    unsigned long long* cand=&g_cand[(size_t)g*CAPB];
    __shared__ unsigned long long sc[4096];
    __shared__ unsigned long long wmax[8];
    __shared__ int wpos[8];
    const int tid=threadIdx.x, lane=tid&31, wid=tid>>5;
    const bool cached = cnt<=4096;
    if(cached) for(int i=tid;i<cnt;i+=256) sc[i]=cand[i];
    __syncthreads();
    unsigned long long* src = cached? sc : cand;
    for(int r=0;r<DPI;r++){
        unsigned long long mk=0ULL; int mp=-1;
        for(int i=tid;i<cnt;i+=256){
            unsigned long long k=src[i];
            if(k>mk){mk=k;mp=i;}
        }
#pragma unroll
        for(int off=16;off>0;off>>=1){
            unsigned long long ok=__shfl_down_sync(0xFFFFFFFFu,mk,off);
            int op=__shfl_down_sync(0xFFFFFFFFu,mp,off);
            if(ok>mk){mk=ok;mp=op;}
        }
        if(lane==0){wmax[wid]=mk;wpos[wid]=mp;}
        __syncthreads();
        if(tid==0){
            unsigned long long bk=wmax[0]; int bp=wpos[0];
#pragma unroll
            for(int w=1;w<8;w++) if(wmax[w]>bk){bk=wmax[w];bp=wpos[w];}
            g_sel[g*DPI+r]=bk;
            if(bp>=0) src[bp]=0ULL;
        }
        __syncthreads();
    }
}

__global__ void decode_k(const float* __restrict__ reg,
                         const int* __restrict__ ph,const int* __restrict__ pw){
    const int g=blockIdx.x, b=g>>2, lvl=g&3;
    const int r=threadIdx.x;
    if(r>=DPI) return;
    const int W=cb_W[lvl], HW=cb_HW[lvl];
    const float ih=(float)(*ph), iw=(float)(*pw);
    const int slot=b*400+lvl*DPI+r;
    unsigned long long k=g_sel[g*DPI+r];
    float* bx=&g_cbox[(size_t)slot*4];
    if(!k){ g_cscore[slot]=-1.f; g_clab[slot]=-1; bx[0]=bx[1]=bx[2]=bx[3]=0.f; return; }
    float sc=unfkey((unsigned)(k>>32));
    unsigned n=0xFFFFFFFFu-(unsigned)(k&0xFFFFFFFFu);
    int pix=(int)(n/CLS_C); int co=(int)(n-(unsigned)pix*CLS_C);
    int a=co/NC, c=co-a*NC;
    int hh=pix/W, ww=pix-hh*W;
    float size=c_sizes[lvl][a%3];
    float hr=sqrtf(c_ratios[a/3]);
    float wr=1.f/hr;
    float ws=wr*size, hs=hr*size;
    float st=(float)c_str[lvl];
    float sx=(float)ww*st, sy=(float)hh*st;
    float ax1=fminf(fmaxf(sx+rintf(-ws*0.5f),0.f),iw);
    float ay1=fminf(fmaxf(sy+rintf(-hs*0.5f),0.f),ih);
    float ax2=fminf(fmaxf(sx+rintf( ws*0.5f),0.f),iw);
    float ay2=fminf(fmaxf(sy+rintf( hs*0.5f),0.f),ih);
    float aw=ax2-ax1, ah=ay2-ay1;
    float cx=ax1+0.5f*aw, cy=ay1+0.5f*ah;
    const float* R=reg + (size_t)REG_C*4*cb_CUM[lvl] + (size_t)b*REG_C*HW;
    float dx=R[(a*4+0)*HW+pix];
    float dy=R[(a*4+1)*HW+pix];
    const float CLIPV=(float)4.135166556742356;
    float dw=fminf(R[(a*4+2)*HW+pix],CLIPV);
    float dh=fminf(R[(a*4+3)*HW+pix],CLIPV);
    float pcx=dx*aw+cx, pcy=dy*ah+cy;
    float pw_=expf(dw)*aw, ph_=expf(dh)*ah;
    bx[0]=fminf(fmaxf(pcx-0.5f*pw_,0.f),iw);
    bx[1]=fminf(fmaxf(pcy-0.5f*ph_,0.f),ih);
    bx[2]=fminf(fmaxf(pcx+0.5f*pw_,0.f),iw);
    bx[3]=fminf(fmaxf(pcy+0.5f*ph_,0.f),ih);
    g_cscore[slot]=sc;
    g_clab[slot]=c;
}

__global__ __launch_bounds__(512)
void final_k(float* __restrict__ out,const int* __restrict__ ph,const int* __restrict__ pw){
    int b=blockIdx.x, tid=threadIdx.x;
    __shared__ unsigned long long key[512];
    __shared__ float X1[512],Y1[512],X2[512],Y2[512],AR[512],SC[512];
    __shared__ float BX1[512],BY1[512],BX2[512],BY2[512];
    __shared__ int LB[512];
    __shared__ unsigned char KP[512];
    float ih=(float)(*ph), iw=(float)(*pw);
    float ob=fmaxf(ih,iw)+1.f;
    if(tid<400)
        key[tid]=((unsigned long long)fkey(g_cscore[b*400+tid])<<32)|(0xFFFFFFFFu-(unsigned)tid);
    else key[tid]=0ULL;
    __syncthreads();
    for(int k=2;k<=512;k<<=1)
        for(int j=k>>1;j>0;j>>=1){
            int ix=tid^j;
            if(ix>tid){
                unsigned long long a=key[tid],c=key[ix];
                if((a>c)==((tid&k)==0)){key[tid]=c;key[ix]=a;}
            }
            __syncthreads();
        }
    {
        unsigned long long k=key[511-tid];
        float sc=-1.f; int lb=-1; float b0=0,b1=0,b2=0,b3=0;
        if(k){
            unsigned i=0xFFFFFFFFu-(unsigned)(k&0xFFFFFFFFu);
            sc=unfkey((unsigned)(k>>32));
            lb=g_clab[b*400+i];
            const float* bp=&g_cbox[((size_t)b*400+i)*4];
            b0=bp[0];b1=bp[1];b2=bp[2];b3=bp[3];
        }
        float o=(float)lb*ob;
        BX1[tid]=b0;BY1[tid]=b1;BX2[tid]=b2;BY2[tid]=b3;
        X1[tid]=b0+o;Y1[tid]=b1+o;X2[tid]=b2+o;Y2[tid]=b3+o;
        SC[tid]=sc;LB[tid]=lb;
        AR[tid]=(X2[tid]-X1[tid])*(Y2[tid]-Y1[tid]);
        KP[tid]=(sc>0.05f)?1:0;
    }
    __syncthreads();
    for(int i=0;i<400;i++){
        if(KP[i]&&tid>i&&tid<400&&KP[tid]){
            float w=fmaxf(fminf(X2[i],X2[tid])-fmaxf(X1[i],X1[tid]),0.f);
            float h=fmaxf(fminf(Y2[i],Y2[tid])-fmaxf(Y1[i],Y1[tid]),0.f);
            float it=w*h;
            float iou=it/(AR[i]+AR[tid]-it+1e-9f);
            if(iou>0.5f) KP[tid]=0;
        }
        __syncthreads();
    }
    if(tid==0){
        int o=0;
        for(int r=0;r<400&&o<DPI;r++) if(KP[r]){
            out[(b*DPI+o)*4+0]=BX1[r]; out[(b*DPI+o)*4+1]=BY1[r];
            out[(b*DPI+o)*4+2]=BX2[r]; out[(b*DPI+o)*4+3]=BY2[r];
            out[1600+b*DPI+o]=SC[r];   out[2000+b*DPI+o]=(float)LB[r];
            o++;
        }
        for(;o<DPI;o++){
            out[(b*DPI+o)*4+0]=0.f; out[(b*DPI+o)*4+1]=0.f;
            out[(b*DPI+o)*4+2]=0.f; out[(b*DPI+o)*4+3]=0.f;
            out[1600+b*DPI+o]=0.f;  out[2000+b*DPI+o]=-1.f;
        }
    }
}

extern "C" void kernel_launch(void* const* d_in, const int* in_sizes, int n_in,
                              void* d_out, int out_size){
    const float* f0=(const float*)d_in[0];
    const float* f1=(const float*)d_in[1];
    const float* f2=(const float*)d_in[2];
    const float* f3=(const float*)d_in[3];
    const float* ctw=(const float*)d_in[4];
    const float* ctb=(const float*)d_in[5];
    const float* cow=(const float*)d_in[6];
    const float* cob=(const float*)d_in[7];
    const float* rtw=(const float*)d_in[8];
    const float* rtb=(const float*)d_in[9];
    const float* row_=(const float*)d_in[10];
    const float* rob=(const float*)d_in[11];
    const int* ph=(const int*)d_in[12];
    const int* pw=(const int*)d_in[13];

    __half *xh0,*xl0,*xh1,*xl1,*wh,*wl;
    float *cls,*reg;
    cudaGetSymbolAddress((void**)&xh0,g_xh0);
    cudaGetSymbolAddress((void**)&xl0,g_xl0);
    cudaGetSymbolAddress((void**)&xh1,g_xh1);
    cudaGetSymbolAddress((void**)&xl1,g_xl1);
    cudaGetSymbolAddress((void**)&cls,g_cls);
    cudaGetSymbolAddress((void**)&reg,g_reg);
    cudaGetSymbolAddress((void**)&wh,g_wth);
    cudaGetSymbolAddress((void**)&wl,g_wtl);

    cudaFuncSetAttribute(conv_tower_k, cudaFuncAttributeMaxDynamicSharedMemorySize, SMEMBYTES);
    cudaFuncSetAttribute(conv_head_k,  cudaFuncAttributeMaxDynamicSharedMemorySize, SMEMBYTES);

    prep_k<<<2048,256>>>(f0,f1,f2,f3,xh0,xl0);
    wtrans_k<<<2048,256>>>(ctw, wh+OFF_CLS_TW, wl+OFF_CLS_TW, 256,2,4);
    wtrans_k<<<2048,256>>>(rtw, wh+OFF_REG_TW, wl+OFF_REG_TW, 256,2,4);
    wtrans_k<<<2048,256>>>(cow, wh+OFF_CLS_OW, wl+OFF_CLS_OW, 720,6,1);
    wtrans_k<<<1024,256>>>(row_, wh+OFF_REG_OW, wl+OFF_REG_OW, 36,1,1);

    const size_t LSZ = 589824;
    conv_tower_k<<<dim3(43,4,BATCH),256,SMEMBYTES>>>(xh0,xl0,
        wh+OFF_CLS_TW+0*LSZ, wl+OFF_CLS_TW+0*LSZ,
        wh+OFF_REG_TW+0*LSZ, wl+OFF_REG_TW+0*LSZ, ctb+0,  rtb+0,  xh1,xl1, 1);
    conv_tower_k<<<dim3(43,4,BATCH),256,SMEMBYTES>>>(xh1,xl1,
        wh+OFF_CLS_TW+1*LSZ, wl+OFF_CLS_TW+1*LSZ,
        wh+OFF_REG_TW+1*LSZ, wl+OFF_REG_TW+1*LSZ, ctb+256,rtb+256,xh0,xl0, 0);
    conv_tower_k<<<dim3(43,4,BATCH),256,SMEMBYTES>>>(xh0,xl0,
        wh+OFF_CLS_TW+2*LSZ, wl+OFF_CLS_TW+2*LSZ,
        wh+OFF_REG_TW+2*LSZ, wl+OFF_REG_TW+2*LSZ, ctb+512,rtb+512,xh1,xl1, 0);
    conv_tower_k<<<dim3(43,4,BATCH),256,SMEMBYTES>>>(xh1,xl1,
        wh+OFF_CLS_TW+3*LSZ, wl+OFF_CLS_TW+3*LSZ,
        wh+OFF_REG_TW+3*LSZ, wl+OFF_REG_TW+3*LSZ, ctb+768,rtb+768,xh0,xl0, 0);
    conv_head_k<<<dim3(43,7,BATCH),256,SMEMBYTES>>>(xh0,xl0,
        wh+OFF_CLS_OW, wl+OFF_CLS_OW, wh+OFF_REG_OW, wl+OFF_REG_OW,
        cob, rob, cls, reg);

    zero_k<<<4096,256>>>();
    hist_k<<<dim3(256,16),256>>>(cls);
    scan_k<<<16,256>>>();
    collect_k<<<dim3(256,16),256>>>(cls);
    select_k<<<16,256>>>();
    decode_k<<<16,128>>>(reg,ph,pw);
    final_k<<<BATCH,512>>>((float*)d_out,ph,pw);
}

// round 17
// speedup vs baseline: 2.4063x; 1.0015x over previous
#include <cuda_runtime.h>
#include <cuda_fp16.h>
#include <math.h>

#define NC 80
#define CLS_C 720
#define REG_C 36
#define DPI 100
#define BATCH 4
#define CAPB 131072

__constant__ int cb_W[4]   = {64,32,16,8};
__constant__ int cb_HW[4]  = {4096,1024,256,64};
__constant__ int cb_LW[4]  = {6,5,4,3};
__constant__ int cb_CUM[4] = {0,4096,5120,5376};
__constant__ int cb_lvl[43] = {0,0,0,0,0,0,0,0,0,0,0,0,0,0,0,0,
                               0,0,0,0,0,0,0,0,0,0,0,0,0,0,0,0,
                               1,1,1,1,1,1,1,1, 2,2, 3};
__constant__ int cb_pix[43] = {0,128,256,384,512,640,768,896,1024,1152,1280,1408,
                               1536,1664,1792,1920,2048,2176,2304,2432,2560,2688,
                               2816,2944,3072,3200,3328,3456,3584,3712,3840,3968,
                               0,128,256,384,512,640,768,896, 0,128, 0};

__device__ __constant__ float c_sizes[4][3] = {
    {32.f,40.f,50.f},{64.f,80.f,101.f},{128.f,161.f,203.f},{256.f,322.f,406.f}};
__device__ __constant__ float c_ratios[3] = {0.5f,1.0f,2.0f};
__device__ __constant__ int   c_str[4] = {8,16,32,64};

#define OFF_CLS_TW 0
#define OFF_REG_TW 2359296
#define OFF_CLS_OW 4718592
#define OFF_REG_OW 6488064
#define WT_TOTAL   6782976

__device__ __align__(16) __half g_xh0[(size_t)8*5440*256];
__device__ __align__(16) __half g_xl0[(size_t)8*5440*256];
__device__ __align__(16) __half g_xh1[(size_t)8*5440*256];
__device__ __align__(16) __half g_xl1[(size_t)8*5440*256];
__device__ __align__(16) __half g_wth[WT_TOTAL];
__device__ __align__(16) __half g_wtl[WT_TOTAL];
__device__ __align__(16) float g_cls[BATCH*CLS_C*5440];
__device__ __align__(16) float g_reg[BATCH*REG_C*5440];
__device__ unsigned g_hist[16*65536];
__device__ unsigned g_thr[16];
__device__ int      g_cnt[16];
__device__ unsigned long long g_cand[(size_t)16*CAPB];
__device__ unsigned long long g_sel[16*DPI];
__device__ float g_cbox[BATCH*400*4];
__device__ float g_cscore[BATCH*400];
__device__ int   g_clab[BATCH*400];

__device__ __forceinline__ unsigned fkey(float f){
    unsigned b=__float_as_uint(f);
    return b ^ ((b>>31) ? 0xFFFFFFFFu : 0x80000000u);
}
__device__ __forceinline__ float unfkey(unsigned u){
    unsigned b=u ^ ((u>>31) ? 0x80000000u : 0xFFFFFFFFu);
    return __uint_as_float(b);
}
__device__ __forceinline__ void mma_f16(float* c, const uint4& a,
                                        unsigned b0, unsigned b1){
    asm("mma.sync.aligned.m16n8k16.row.col.f32.f16.f16.f32 "
        "{%0,%1,%2,%3},{%4,%5,%6,%7},{%8,%9},{%0,%1,%2,%3};"
        : "+f"(c[0]),"+f"(c[1]),"+f"(c[2]),"+f"(c[3])
        : "r"(a.x),"r"(a.y),"r"(a.z),"r"(a.w),"r"(b0),"r"(b1));
}
__device__ __forceinline__ unsigned smem_u32(const void* p){
    unsigned a;
    asm("{ .reg .u64 t; cvta.to.shared.u64 t, %1; cvt.u32.u64 %0, t; }"
        : "=r"(a) : "l"(p));
    return a;
}
__device__ __forceinline__ void cp16(unsigned dst, const void* src, int sz){
    asm volatile("cp.async.cg.shared.global [%0], [%1], 16, %2;"
                 :: "r"(dst), "l"(src), "r"(sz));
}
#define CP_COMMIT() asm volatile("cp.async.commit_group;" ::: "memory")
#define CP_WAIT0()  asm volatile("cp.async.wait_group 0;" ::: "memory")
#define CP_WAIT1()  asm volatile("cp.async.wait_group 1;" ::: "memory")

__global__ void prep_k(const float* __restrict__ f0,const float* __restrict__ f1,
                       const float* __restrict__ f2,const float* __restrict__ f3,
                       __half* __restrict__ oh,__half* __restrict__ ol){
    size_t total=(size_t)4*5440*256;
    for(size_t e=(size_t)blockIdx.x*blockDim.x+threadIdx.x;e<total;
        e+=(size_t)gridDim.x*blockDim.x){
        int ci=(int)(e&255);
        int pixG=(int)((e>>8)%5440);
        int b=(int)(e/(5440*256));
        int lvl = pixG<4096?0 : pixG<5120?1 : pixG<5376?2 : 3;
        int cum = lvl==0?0 : lvl==1?4096 : lvl==2?5120 : 5376;
        int HW  = lvl==0?4096 : lvl==1?1024 : lvl==2?256 : 64;
        const float* f = lvl==0?f0 : lvl==1?f1 : lvl==2?f2 : f3;
        float v = f[((size_t)b*256+ci)*HW + (pixG-cum)];
        __half h=__float2half(v);
        oh[e]=h; ol[e]=__float2half(v-__half2float(h));
    }
}

__global__ void wtrans_k(const float* __restrict__ src,
                         __half* __restrict__ dh, __half* __restrict__ dl,
                         int Cout,int nTiles,int nL){
    size_t total=(size_t)nL*9*nTiles*32768;
    for(size_t e=(size_t)blockIdx.x*blockDim.x+threadIdx.x;e<total;
        e+=(size_t)gridDim.x*blockDim.x){
        int h2=(int)(e&1);
        size_t s=e>>1;
        int v=(int)(s&3);
        int lane=(int)((s>>2)&31);
        int fm=(int)((s>>7)&3);
        int wm=(int)((s>>9)&1);
        int ki=(int)((s>>10)&1);
        int cchunk=(int)((s>>11)&7);
        size_t t=s>>14;
        int ct=(int)(t%nTiles); t/=nTiles;
        int kpos=(int)(t%9); int layer=(int)(t/9);
        int lr=lane>>2, lc=lane&3;
        int co=ct*128 + wm*64 + fm*16 + (v&1)*8 + lr;
        int k =cchunk*32 + ki*16 + (v>>1)*8 + 2*lc + h2;
        float val=0.f;
        if(co<Cout) val=src[(((size_t)layer*Cout+co)*256+k)*9+kpos];
        __half hi=__float2half(val);
        dh[e]=hi; dl[e]=__float2half(val-__half2float(hi));
    }
}

// 3xFP16 m16n8k16 conv core, 3-stage cp.async ring, 2 blocks/SM.
#define STAGEB 36864
#define SMEMBYTES (3*STAGEB)

__device__ void conv_mma(
    const __half* __restrict__ Xh, const __half* __restrict__ Xl,
    const __half* __restrict__ Whh, const __half* __restrict__ Whl,
    int nTiles, int ct, const float* __restrict__ bias,
    int W, int HW, int lw, int pixBase,
    int mode, int Cout, int relu,
    __half* __restrict__ outH, __half* __restrict__ outL,
    float* __restrict__ outF,
    int cum, char* smem)
{
    Xh += (size_t)cum*256;
    Xl += (size_t)cum*256;

    const int tid=threadIdx.x;
    const int lane=tid&31, wid=tid>>5;
    const int wm=wid&1, wn=wid>>1;
    const int lr=lane>>2, lc=lane&3;
    const int coBase=ct*128;

    int validPx = HW - pixBase; if(validPx>128) validPx=128;

    const int srow=tid>>1, half=tid&1;
    const int q=pixBase+srow;
    const bool rowv = srow<validPx;
    const int hh=q>>lw, ww=q&(W-1);

    const unsigned sb = smem_u32(smem);

    float acc[4][4][4];
#pragma unroll
    for(int i=0;i<4;i++)
#pragma unroll
        for(int j=0;j<4;j++)
#pragma unroll
            for(int r=0;r<4;r++) acc[i][j][r]=0.f;

    auto stage=[&](int ch,int s){
        const int kpos=ch>>3, cc=ch&7;
        const unsigned base = sb + (unsigned)(s*STAGEB);
        const __half* awh=Whh + ((size_t)(kpos*nTiles+ct))*32768 + cc*4096 + tid*16;
        const __half* awl=Whl + ((size_t)(kpos*nTiles+ct))*32768 + cc*4096 + tid*16;
        cp16(base + tid*32,          awh,   16);
        cp16(base + tid*32+16,       awh+8, 16);
        cp16(base + 8192 + tid*32,   awl,   16);
        cp16(base + 8192 + tid*32+16,awl+8, 16);
        const int dh=kpos/3-1, dw=kpos-(kpos/3)*3-1;
        const int hs=hh+dh, ws=ww+dw;
        const bool ok = rowv && (unsigned)hs<(unsigned)W && (unsigned)ws<(unsigned)W;
        const size_t xoff = ok ? ((size_t)(hs*W+ws)*256) : 0;
        const int sz = ok?16:0;
        const __half* xh = Xh + xoff + cc*32 + half*16;
        const __half* xl = Xl + xoff + cc*32 + half*16;
        const unsigned bh = base + 16384 + (unsigned)((srow*40 + half*16)*2);
        const unsigned bl = base + 26624 + (unsigned)((srow*40 + half*16)*2);
        cp16(bh,    xh,   sz);
        cp16(bh+16, xh+8, sz);
        cp16(bl,    xl,   sz);
        cp16(bl+16, xl+8, sz);
    };

    stage(0,0); CP_COMMIT();
    stage(1,1); CP_COMMIT();

    int sbuf=0;
    for(int ch=0;ch<72;ch++){
        if(ch<71) CP_WAIT1(); else CP_WAIT0();
        __syncthreads();
        if(ch+2<72){
            int nb=sbuf+2; if(nb>=3) nb-=3;
            stage(ch+2, nb); CP_COMMIT();
        }
        char* S = smem + sbuf*STAGEB;
        sbuf++; if(sbuf>=3) sbuf=0;
#pragma unroll
        for(int ki=0;ki<2;ki++){
            uint4 AH[4], AL[4];
#pragma unroll
            for(int fm=0;fm<4;fm++){
                const int fo=((((ki*2+wm)*4+fm)*32+lane))*16;
                AH[fm]=*(const uint4*)(S + fo);
                AL[fm]=*(const uint4*)(S + 8192 + fo);
            }
#pragma unroll
            for(int fn=0;fn<4;fn++){
                const int nr=(wn<<5)+(fn<<3)+lr;
                const int bo=(nr*40 + ki*16 + 2*lc)*2;
                unsigned bh0=*(const unsigned*)(S + 16384 + bo);
                unsigned bh1=*(const unsigned*)(S + 16384 + bo + 16);
                unsigned bl0=*(const unsigned*)(S + 26624 + bo);
                unsigned bl1=*(const unsigned*)(S + 26624 + bo + 16);
#pragma unroll
                for(int fm=0;fm<4;fm++){
                    mma_f16(acc[fm][fn], AH[fm], bh0, bh1);
                    mma_f16(acc[fm][fn], AH[fm], bl0, bl1);
                    mma_f16(acc[fm][fn], AL[fm], bh0, bh1);
                }
            }
        }
    }

#pragma unroll
    for(int fm=0;fm<4;fm++){
#pragma unroll
        for(int fn=0;fn<4;fn++){
            int m0=(wm<<6)+(fm<<4)+lr;
            int n0=(wn<<5)+(fn<<3)+(lc<<1);
            const float* a=acc[fm][fn];
#pragma unroll
            for(int r=0;r<4;r++){
                int m=m0+((r>>1)<<3);
                int n=n0+(r&1);
                if(n>=validPx) continue;
                int co=coBase+m;
                if(mode==0){
                    float v=a[r]+bias[co];
                    if(relu) v=fmaxf(v,0.f);
                    __half hv=__float2half(v);
                    size_t ad=((size_t)(cum+pixBase+n))*256+co;
                    outH[ad]=hv;
                    outL[ad]=__float2half(v-__half2float(hv));
                }else{
                    if(co<Cout)
                        outF[(size_t)co*HW + pixBase + n]=a[r]+bias[co];
                }
            }
        }
    }
}

__global__ __launch_bounds__(256,2)
void conv_tower_k(const __half* __restrict__ Xh,const __half* __restrict__ Xl,
                  const __half* __restrict__ wCh,const __half* __restrict__ wCl,
                  const __half* __restrict__ wRh,const __half* __restrict__ wRl,
                  const float* __restrict__ bC,const float* __restrict__ bR,
                  __half* __restrict__ XhO,__half* __restrict__ XlO,int first){
    extern __shared__ char smem[];
    const int bx=blockIdx.x;
    const int lvl=cb_lvl[bx], pixBase=cb_pix[bx];
    const int tower=blockIdx.y>>1, ct=blockIdx.y&1;
    const int b=blockIdx.z;
    const int W=cb_W[lvl],HW=cb_HW[lvl],lw=cb_LW[lvl],cum=cb_CUM[lvl];
    int inSlot = first ? b : (tower*4+b);
    int outSlot = tower*4+b;
    conv_mma(Xh+(size_t)inSlot*5440*256, Xl+(size_t)inSlot*5440*256,
             tower?wRh:wCh, tower?wRl:wCl, 2, ct, tower?bR:bC,
             W,HW,lw,pixBase, 0,256,1,
             XhO+(size_t)outSlot*5440*256, XlO+(size_t)outSlot*5440*256,
             0, cum, smem);
}

__global__ __launch_bounds__(256,2)
void conv_head_k(const __half* __restrict__ Xh,const __half* __restrict__ Xl,
                 const __half* __restrict__ wCh,const __half* __restrict__ wCl,
                 const __half* __restrict__ wRh,const __half* __restrict__ wRl,
                 const float* __restrict__ cob,const float* __restrict__ rob,
                 float* __restrict__ cls,float* __restrict__ reg){
    extern __shared__ char smem[];
    const int bx=blockIdx.x;
    const int lvl=cb_lvl[bx], pixBase=cb_pix[bx];
    const int y=blockIdx.y, b=blockIdx.z;
    const int W=cb_W[lvl],HW=cb_HW[lvl],lw=cb_LW[lvl],cum=cb_CUM[lvl];
    if(y<6){
        conv_mma(Xh+(size_t)b*5440*256, Xl+(size_t)b*5440*256,
                 wCh, wCl, 6, y, cob,
                 W,HW,lw,pixBase, 1,720,0, 0,0,
                 cls + (size_t)CLS_C*4*cum + (size_t)b*CLS_C*HW, cum, smem);
    }else{
        conv_mma(Xh+(size_t)(4+b)*5440*256, Xl+(size_t)(4+b)*5440*256,
                 wRh, wRl, 1, 0, rob,
                 W,HW,lw,pixBase, 1,36,0, 0,0,
                 reg + (size_t)REG_C*4*cum + (size_t)b*REG_C*HW, cum, smem);
    }
}

__device__ __forceinline__ float sigm(float v){ return 1.0f/(1.0f+expf(-v)); }
__device__ __forceinline__ bool is_cand(float v){
    if(v>-2.93f) return true;
    if(v<=-2.96f) return false;
    return sigm(v)>0.05f;
}

__global__ void zero_k(){
    int i=blockIdx.x*blockDim.x+threadIdx.x;
    if(i<16*65536) g_hist[i]=0;
    if(i<16) g_cnt[i]=0;
}

__global__ void hist_k(const float* __restrict__ cls){
    const int g=blockIdx.y, b=g>>2, lvl=g&3;
    const int HW=cb_HW[lvl], n=CLS_C*HW;
    const float* p=cls + (size_t)CLS_C*4*cb_CUM[lvl] + (size_t)b*n;
    for(int m=blockIdx.x*blockDim.x+threadIdx.x;m<n;m+=gridDim.x*blockDim.x){
        float v=p[m];
        if(is_cand(v)) atomicAdd(&g_hist[g*65536+(fkey(sigm(v))>>16)],1u);
    }
}

__global__ void scan_k(){
    const int g=blockIdx.x;
    __shared__ unsigned seg[256];
    const unsigned* h=&g_hist[g*65536];
    unsigned s=0; int base=threadIdx.x*256;
    for(int k=0;k<256;k++) s+=h[65535-(base+k)];
    seg[threadIdx.x]=s;
    __syncthreads();
    if(threadIdx.x==0){
        unsigned cum=0,thr=0;
        for(int sg=0;sg<256;sg++){
            if(cum+seg[sg]>=DPI){
                for(int k=0;k<256;k++){
                    cum+=h[65535-(sg*256+k)];
                    if(cum>=DPI){thr=65535-(sg*256+k);break;}
                }
                break;
            }
            cum+=seg[sg];
        }
        g_thr[g]=thr;
    }
}

__global__ void collect_k(const float* __restrict__ cls){
    const int g=blockIdx.y, b=g>>2, lvl=g&3;
    const int HW=cb_HW[lvl], n=CLS_C*HW;
    const unsigned thr=g_thr[g];
    const float* p=cls + (size_t)CLS_C*4*cb_CUM[lvl] + (size_t)b*n;
    for(int m=blockIdx.x*blockDim.x+threadIdx.x;m<n;m+=gridDim.x*blockDim.x){
        float v=p[m];
        if(!is_cand(v)) continue;
        unsigned u=fkey(sigm(v));
        if((u>>16)>=thr){
            int pos=atomicAdd(&g_cnt[g],1);
            if(pos<CAPB){
                int co=m/HW, pix=m-co*HW;
                unsigned nn=(unsigned)(pix*CLS_C+co);
                g_cand[(size_t)g*CAPB+pos]=((unsigned long long)u<<32)|(0xFFFFFFFFu-nn);
            }
        }
    }
}

__global__ __launch_bounds__(256)
void select_k(){
    const int g=blockIdx.x;
    int cnt=g_cnt[g]; if(cnt>CAPB) cnt=CAPB;
    unsigned long long* cand=&g_cand[(size_t)g*CAPB];
    __shared__ unsigned long long sc[4096];
    __shared__ unsigned long long wmax[8];
    __shared__ int wpos[8];
    const int tid=threadIdx.x, lane=tid&31, wid=tid>>5;
    const bool cached = cnt<=4096;
    if(cached) for(int i=tid;i<cnt;i+=256) sc[i]=cand[i];
    __syncthreads();
    unsigned long long* src = cached? sc : cand;
    for(int r=0;r<DPI;r++){
        unsigned long long mk=0ULL; int mp=-1;
        for(int i=tid;i<cnt;i+=256){
            unsigned long long k=src[i];
            if(k>mk){mk=k;mp=i;}
        }
#pragma unroll
        for(int off=16;off>0;off>>=1){
            unsigned long long ok=__shfl_down_sync(0xFFFFFFFFu,mk,off);
            int op=__shfl_down_sync(0xFFFFFFFFu,mp,off);
            if(ok>mk){mk=ok;mp=op;}
        }
        if(lane==0){wmax[wid]=mk;wpos[wid]=mp;}
        __syncthreads();
        if(tid==0){
            unsigned long long bk=wmax[0]; int bp=wpos[0];
#pragma unroll
            for(int w=1;w<8;w++) if(wmax[w]>bk){bk=wmax[w];bp=wpos[w];}
            g_sel[g*DPI+r]=bk;
            if(bp>=0) src[bp]=0ULL;
        }
        __syncthreads();
    }
}

__global__ void decode_k(const float* __restrict__ reg,
                         const int* __restrict__ ph,const int* __restrict__ pw){
    const int g=blockIdx.x, b=g>>2, lvl=g&3;
    const int r=threadIdx.x;
    if(r>=DPI) return;
    const int W=cb_W[lvl], HW=cb_HW[lvl];
    const float ih=(float)(*ph), iw=(float)(*pw);
    const int slot=b*400+lvl*DPI+r;
    unsigned long long k=g_sel[g*DPI+r];
    float* bx=&g_cbox[(size_t)slot*4];
    if(!k){ g_cscore[slot]=-1.f; g_clab[slot]=-1; bx[0]=bx[1]=bx[2]=bx[3]=0.f; return; }
    float sc=unfkey((unsigned)(k>>32));
    unsigned n=0xFFFFFFFFu-(unsigned)(k&0xFFFFFFFFu);
    int pix=(int)(n/CLS_C); int co=(int)(n-(unsigned)pix*CLS_C);
    int a=co/NC, c=co-a*NC;
    int hh=pix/W, ww=pix-hh*W;
    float size=c_sizes[lvl][a%3];
    float hr=sqrtf(c_ratios[a/3]);
    float wr=1.f/hr;
    float ws=wr*size, hs=hr*size;
    float st=(float)c_str[lvl];
    float sx=(float)ww*st, sy=(float)hh*st;
    float ax1=fminf(fmaxf(sx+rintf(-ws*0.5f),0.f),iw);
    float ay1=fminf(fmaxf(sy+rintf(-hs*0.5f),0.f),ih);
    float ax2=fminf(fmaxf(sx+rintf( ws*0.5f),0.f),iw);
    float ay2=fminf(fmaxf(sy+rintf( hs*0.5f),0.f),ih);
    float aw=ax2-ax1, ah=ay2-ay1;
    float cx=ax1+0.5f*aw, cy=ay1+0.5f*ah;
    const float* R=reg + (size_t)REG_C*4*cb_CUM[lvl] + (size_t)b*REG_C*HW;
    float dx=R[(a*4+0)*HW+pix];
    float dy=R[(a*4+1)*HW+pix];
    const float CLIPV=(float)4.135166556742356;
    float dw=fminf(R[(a*4+2)*HW+pix],CLIPV);
    float dh=fminf(R[(a*4+3)*HW+pix],CLIPV);
    float pcx=dx*aw+cx, pcy=dy*ah+cy;
    float pw_=expf(dw)*aw, ph_=expf(dh)*ah;
    bx[0]=fminf(fmaxf(pcx-0.5f*pw_,0.f),iw);
    bx[1]=fminf(fmaxf(pcy-0.5f*ph_,0.f),ih);
    bx[2]=fminf(fmaxf(pcx+0.5f*pw_,0.f),iw);
    bx[3]=fminf(fmaxf(pcy+0.5f*ph_,0.f),ih);
    g_cscore[slot]=sc;
    g_clab[slot]=c;
}

__global__ __launch_bounds__(512)
void final_k(float* __restrict__ out,const int* __restrict__ ph,const int* __restrict__ pw){
    int b=blockIdx.x, tid=threadIdx.x;
    __shared__ unsigned long long key[512];
    __shared__ float X1[512],Y1[512],X2[512],Y2[512],AR[512],SC[512];
    __shared__ float BX1[512],BY1[512],BX2[512],BY2[512];
    __shared__ int LB[512];
    __shared__ unsigned char KP[512];
    float ih=(float)(*ph), iw=(float)(*pw);
    float ob=fmaxf(ih,iw)+1.f;
    if(tid<400)
        key[tid]=((unsigned long long)fkey(g_cscore[b*400+tid])<<32)|(0xFFFFFFFFu-(unsigned)tid);
    else key[tid]=0ULL;
    __syncthreads();
    for(int k=2;k<=512;k<<=1)
        for(int j=k>>1;j>0;j>>=1){
            int ix=tid^j;
            if(ix>tid){
                unsigned long long a=key[tid],c=key[ix];
                if((a>c)==((tid&k)==0)){key[tid]=c;key[ix]=a;}
            }
            __syncthreads();
        }
    {
        unsigned long long k=key[511-tid];
        float sc=-1.f; int lb=-1; float b0=0,b1=0,b2=0,b3=0;
        if(k){
            unsigned i=0xFFFFFFFFu-(unsigned)(k&0xFFFFFFFFu);
            sc=unfkey((unsigned)(k>>32));
            lb=g_clab[b*400+i];
            const float* bp=&g_cbox[((size_t)b*400+i)*4];
            b0=bp[0];b1=bp[1];b2=bp[2];b3=bp[3];
        }
        float o=(float)lb*ob;
        BX1[tid]=b0;BY1[tid]=b1;BX2[tid]=b2;BY2[tid]=b3;
        X1[tid]=b0+o;Y1[tid]=b1+o;X2[tid]=b2+o;Y2[tid]=b3+o;
        SC[tid]=sc;LB[tid]=lb;
        AR[tid]=(X2[tid]-X1[tid])*(Y2[tid]-Y1[tid]);
        KP[tid]=(sc>0.05f)?1:0;
    }
    __syncthreads();
    for(int i=0;i<400;i++){
        if(KP[i]&&tid>i&&tid<400&&KP[tid]){
            float w=fmaxf(fminf(X2[i],X2[tid])-fmaxf(X1[i],X1[tid]),0.f);
            float h=fmaxf(fminf(Y2[i],Y2[tid])-fmaxf(Y1[i],Y1[tid]),0.f);
            float it=w*h;
            float iou=it/(AR[i]+AR[tid]-it+1e-9f);
            if(iou>0.5f) KP[tid]=0;
        }
        __syncthreads();
    }
    if(tid==0){
        int o=0;
        for(int r=0;r<400&&o<DPI;r++) if(KP[r]){
            out[(b*DPI+o)*4+0]=BX1[r]; out[(b*DPI+o)*4+1]=BY1[r];
            out[(b*DPI+o)*4+2]=BX2[r]; out[(b*DPI+o)*4+3]=BY2[r];
            out[1600+b*DPI+o]=SC[r];   out[2000+b*DPI+o]=(float)LB[r];
            o++;
        }
        for(;o<DPI;o++){
            out[(b*DPI+o)*4+0]=0.f; out[(b*DPI+o)*4+1]=0.f;
            out[(b*DPI+o)*4+2]=0.f; out[(b*DPI+o)*4+3]=0.f;
            out[1600+b*DPI+o]=0.f;  out[2000+b*DPI+o]=-1.f;
        }
    }
}

extern "C" void kernel_launch(void* const* d_in, const int* in_sizes, int n_in,
                              void* d_out, int out_size){
    const float* f0=(const float*)d_in[0];
    const float* f1=(const float*)d_in[1];
    const float* f2=(const float*)d_in[2];
    const float* f3=(const float*)d_in[3];
    const float* ctw=(const float*)d_in[4];
    const float* ctb=(const float*)d_in[5];
    const float* cow=(const float*)d_in[6];
    const float* cob=(const float*)d_in[7];
    const float* rtw=(const float*)d_in[8];
    const float* rtb=(const float*)d_in[9];
    const float* row_=(const float*)d_in[10];
    const float* rob=(const float*)d_in[11];
    const int* ph=(const int*)d_in[12];
    const int* pw=(const int*)d_in[13];

    __half *xh0,*xl0,*xh1,*xl1,*wh,*wl;
    float *cls,*reg;
    cudaGetSymbolAddress((void**)&xh0,g_xh0);
    cudaGetSymbolAddress((void**)&xl0,g_xl0);
    cudaGetSymbolAddress((void**)&xh1,g_xh1);
    cudaGetSymbolAddress((void**)&xl1,g_xl1);
    cudaGetSymbolAddress((void**)&cls,g_cls);
    cudaGetSymbolAddress((void**)&reg,g_reg);
    cudaGetSymbolAddress((void**)&wh,g_wth);
    cudaGetSymbolAddress((void**)&wl,g_wtl);

    cudaFuncSetAttribute(conv_tower_k, cudaFuncAttributeMaxDynamicSharedMemorySize, SMEMBYTES);
    cudaFuncSetAttribute(conv_head_k,  cudaFuncAttributeMaxDynamicSharedMemorySize, SMEMBYTES);

    prep_k<<<2048,256>>>(f0,f1,f2,f3,xh0,xl0);
    wtrans_k<<<2048,256>>>(ctw, wh+OFF_CLS_TW, wl+OFF_CLS_TW, 256,2,4);
    wtrans_k<<<2048,256>>>(rtw, wh+OFF_REG_TW, wl+OFF_REG_TW, 256,2,4);
    wtrans_k<<<2048,256>>>(cow, wh+OFF_CLS_OW, wl+OFF_CLS_OW, 720,6,1);
    wtrans_k<<<1024,256>>>(row_, wh+OFF_REG_OW, wl+OFF_REG_OW, 36,1,1);

    const size_t LSZ = 589824;
    conv_tower_k<<<dim3(43,4,BATCH),256,SMEMBYTES>>>(xh0,xl0,
        wh+OFF_CLS_TW+0*LSZ, wl+OFF_CLS_TW+0*LSZ,
        wh+OFF_REG_TW+0*LSZ, wl+OFF_REG_TW+0*LSZ, ctb+0,  rtb+0,  xh1,xl1, 1);
    conv_tower_k<<<dim3(43,4,BATCH),256,SMEMBYTES>>>(xh1,xl1,
        wh+OFF_CLS_TW+1*LSZ, wl+OFF_CLS_TW+1*LSZ,
        wh+OFF_REG_TW+1*LSZ, wl+OFF_REG_TW+1*LSZ, ctb+256,rtb+256,xh0,xl0, 0);
    conv_tower_k<<<dim3(43,4,BATCH),256,SMEMBYTES>>>(xh0,xl0,
        wh+OFF_CLS_TW+2*LSZ, wl+OFF_CLS_TW+2*LSZ,
        wh+OFF_REG_TW+2*LSZ, wl+OFF_REG_TW+2*LSZ, ctb+512,rtb+512,xh1,xl1, 0);
    conv_tower_k<<<dim3(43,4,BATCH),256,SMEMBYTES>>>(xh1,xl1,
        wh+OFF_CLS_TW+3*LSZ, wl+OFF_CLS_TW+3*LSZ,
        wh+OFF_REG_TW+3*LSZ, wl+OFF_REG_TW+3*LSZ, ctb+768,rtb+768,xh0,xl0, 0);
    conv_head_k<<<dim3(43,7,BATCH),256,SMEMBYTES>>>(xh0,xl0,
        wh+OFF_CLS_OW, wl+OFF_CLS_OW, wh+OFF_REG_OW, wl+OFF_REG_OW,
        cob, rob, cls, reg);

    zero_k<<<4096,256>>>();
    hist_k<<<dim3(256,16),256>>>(cls);
    scan_k<<<16,256>>>();
    collect_k<<<dim3(256,16),256>>>(cls);
    select_k<<<16,256>>>();
    decode_k<<<16,128>>>(reg,ph,pw);
    final_k<<<BATCH,512>>>((float*)d_out,ph,pw);
}